// round 5
// baseline (speedup 1.0000x reference)
#include <cuda_runtime.h>
#include <math.h>
#include <stdint.h>

// Problem sizes (fixed)
#define BATCH 2
#define SEQ   4096
#define DIM   1024
#define MTOT  (BATCH * SEQ)     // 8192
#define DE    (2 * DIM)         // 2048  (cos || sin concatenated)

// ---------------- scratch (device globals; no allocation allowed) ----------
__device__ float g_Q [MTOT * DIM];
__device__ float g_K [MTOT * DIM];
__device__ float g_V [MTOT * DIM];
__device__ float g_Vt[MTOT * DIM];                  // V transposed per batch [DIM, SEQ]
__device__ float g_Qe[MTOT * DE];
__device__ float g_Ke[MTOT * DE];
__device__ float g_S [(size_t)BATCH * SEQ * SEQ];   // scores / weights (134 MB)

// ============================ helpers =======================================
__device__ __forceinline__ uint32_t smem_u32(const void* p) {
    uint32_t a;
    asm("{ .reg .u64 t; cvta.to.shared.u64 t, %1; cvt.u32.u64 %0, t; }"
        : "=r"(a) : "l"(p));
    return a;
}

__device__ __forceinline__ float to_tf32(float x) {
    uint32_t u;
    asm("cvt.rna.tf32.f32 %0, %1;" : "=r"(u) : "f"(x));
    return __uint_as_float(u);
}

__device__ __forceinline__ uint32_t tf32_bits(float x) {
    uint32_t u;
    asm("cvt.rna.tf32.f32 %0, %1;" : "=r"(u) : "f"(x));
    return u;
}

__device__ __forceinline__ void cpasync16(uint32_t saddr, const void* gaddr) {
    asm volatile("cp.async.cg.shared.global [%0], [%1], 16;"
                 :: "r"(saddr), "l"(gaddr) : "memory");
}

__device__ __forceinline__ void mma_tf32(float c[4], const uint32_t a[4],
                                         const uint32_t b[2]) {
    asm volatile(
        "mma.sync.aligned.m16n8k8.row.col.f32.tf32.tf32.f32 "
        "{%0,%1,%2,%3}, {%4,%5,%6,%7}, {%8,%9}, {%0,%1,%2,%3};"
        : "+f"(c[0]), "+f"(c[1]), "+f"(c[2]), "+f"(c[3])
        : "r"(a[0]), "r"(a[1]), "r"(a[2]), "r"(a[3]),
          "r"(b[0]), "r"(b[1]));
}

// ============================================================================
// tf32 tensor-core NT GEMM: C[M,N] = A[M,K] @ B[N,K]^T (+bias), fp32 out.
// CTA tile 128(M) x 256(N) x 32(K); 256 threads = 8 warps (2x4 grid),
// warp tile 64x64; mma.m16n8k8; 4-stage cp.async ring; 1 sync per k-tile.
// SPLIT3: 3xTF32 Karatsuba split for near-fp32 accuracy (used for Q,K proj).
// Smem rows padded to 36 floats: conflict-free fragment LDS.
// Requires: M%128==0, N%256==0, K%32==0.
// ============================================================================
#define STAGE_FLOATS 13824                    // (128 + 256) * 36
#define STAGE_BYTES  55296
#define GEMM_SMEM_BYTES (4 * STAGE_BYTES)     // 221184

template<bool SPLIT3>
__global__ void __launch_bounds__(256, 1)
tc_gemm(const float* __restrict__ A, const float* __restrict__ B,
        const float* __restrict__ bias, float* __restrict__ C,
        int Nld, int K,
        size_t strA, size_t strB, size_t strC)
{
    extern __shared__ float dynsmem[];
    const uint32_t sb = smem_u32(dynsmem);

    const int tid  = threadIdx.x;
    const int wid  = tid >> 5;
    const int lane = tid & 31;

    A += strA * blockIdx.z;
    B += strB * blockIdx.z;
    C += strC * blockIdx.z;
    const int tileM = blockIdx.y * 128;
    const int tileN = blockIdx.x * 256;

    // ---- loader mapping: baseRow = tid>>3 (0..31), seg = tid&7 (16B of 128B row)
    const int baseRow = tid >> 3;
    const int seg     = tid & 7;
    const float* Ath = A + (size_t)(tileM + baseRow) * K + seg * 4;
    const float* Bth = B + (size_t)(tileN + baseRow) * K + seg * 4;
    const uint32_t thoff = (uint32_t)(baseRow * 144 + seg * 16);

#define ISSUE_STAGE(KT, S) do {                                               \
    uint32_t _sa = sb + (uint32_t)(S) * STAGE_BYTES + thoff;                  \
    uint32_t _sbB = _sa + 18432u;                                             \
    const float* _ga = Ath + (size_t)(KT) * 32;                               \
    const float* _gb = Bth + (size_t)(KT) * 32;                               \
    _Pragma("unroll")                                                         \
    for (int _i = 0; _i < 4; _i++)                                            \
        cpasync16(_sa + _i * (32u * 144u), _ga + (size_t)_i * 32 * K);        \
    _Pragma("unroll")                                                         \
    for (int _i = 0; _i < 8; _i++)                                            \
        cpasync16(_sbB + _i * (32u * 144u), _gb + (size_t)_i * 32 * K);       \
    asm volatile("cp.async.commit_group;" ::: "memory");                      \
} while (0)

    const int nkt = K >> 5;
    ISSUE_STAGE(0, 0);
    ISSUE_STAGE(1, 1);
    ISSUE_STAGE(2, 2);

    // ---- compute mapping
    const int warp_m = wid >> 2;       // 0..1 -> 64 rows
    const int warp_n = wid & 3;        // 0..3 -> 64 cols
    const int g   = lane >> 2;         // 0..7
    const int tig = lane & 3;          // 0..3

    float acc[4][8][4];
#pragma unroll
    for (int mi = 0; mi < 4; mi++)
#pragma unroll
        for (int nj = 0; nj < 8; nj++)
#pragma unroll
            for (int r = 0; r < 4; r++) acc[mi][nj][r] = 0.0f;

    int s = 0;
    for (int kt = 0; kt < nkt; ++kt) {
        asm volatile("cp.async.wait_group 2;" ::: "memory");   // tile kt ready
        __syncthreads();   // kt visible to all; all warps done with kt-1's stage

        if (kt + 3 < nkt) {
            ISSUE_STAGE(kt + 3, (kt + 3) & 3);
        } else {
            asm volatile("cp.async.commit_group;" ::: "memory");  // keep count
        }

        const float* sA = dynsmem + s * STAGE_FLOATS;
        const float* sB = sA + 4608;

#pragma unroll
        for (int ks = 0; ks < 4; ++ks) {
            const int kk0 = ks * 8 + tig;
            if (!SPLIT3) {
                uint32_t a[4][4], b[8][2];
#pragma unroll
                for (int mi = 0; mi < 4; mi++) {
                    const float* pa = sA + (size_t)(warp_m * 64 + mi * 16 + g) * 36;
                    a[mi][0] = tf32_bits(pa[kk0]);
                    a[mi][1] = tf32_bits(pa[288 + kk0]);
                    a[mi][2] = tf32_bits(pa[kk0 + 4]);
                    a[mi][3] = tf32_bits(pa[288 + kk0 + 4]);
                }
#pragma unroll
                for (int nj = 0; nj < 8; nj++) {
                    const float* pb = sB + (size_t)(warp_n * 64 + nj * 8 + g) * 36;
                    b[nj][0] = tf32_bits(pb[kk0]);
                    b[nj][1] = tf32_bits(pb[kk0 + 4]);
                }
#pragma unroll
                for (int mi = 0; mi < 4; mi++)
#pragma unroll
                    for (int nj = 0; nj < 8; nj++)
                        mma_tf32(acc[mi][nj], a[mi], b[nj]);
            } else {
                uint32_t ah[4][4], al[4][4], bh[8][2], bl[8][2];
#pragma unroll
                for (int mi = 0; mi < 4; mi++) {
                    const float* pa = sA + (size_t)(warp_m * 64 + mi * 16 + g) * 36;
                    float v0 = pa[kk0],       v1 = pa[288 + kk0];
                    float v2 = pa[kk0 + 4],   v3 = pa[288 + kk0 + 4];
                    ah[mi][0] = tf32_bits(v0); al[mi][0] = tf32_bits(v0 - __uint_as_float(ah[mi][0]));
                    ah[mi][1] = tf32_bits(v1); al[mi][1] = tf32_bits(v1 - __uint_as_float(ah[mi][1]));
                    ah[mi][2] = tf32_bits(v2); al[mi][2] = tf32_bits(v2 - __uint_as_float(ah[mi][2]));
                    ah[mi][3] = tf32_bits(v3); al[mi][3] = tf32_bits(v3 - __uint_as_float(ah[mi][3]));
                }
#pragma unroll
                for (int nj = 0; nj < 8; nj++) {
                    const float* pb = sB + (size_t)(warp_n * 64 + nj * 8 + g) * 36;
                    float w0 = pb[kk0], w1 = pb[kk0 + 4];
                    bh[nj][0] = tf32_bits(w0); bl[nj][0] = tf32_bits(w0 - __uint_as_float(bh[nj][0]));
                    bh[nj][1] = tf32_bits(w1); bl[nj][1] = tf32_bits(w1 - __uint_as_float(bh[nj][1]));
                }
#pragma unroll
                for (int mi = 0; mi < 4; mi++)
#pragma unroll
                    for (int nj = 0; nj < 8; nj++) {
                        mma_tf32(acc[mi][nj], ah[mi], bl[nj]);
                        mma_tf32(acc[mi][nj], al[mi], bh[nj]);
                        mma_tf32(acc[mi][nj], ah[mi], bh[nj]);
                    }
            }
        }
        s = (s + 1) & 3;
    }
#undef ISSUE_STAGE

    // ---- epilogue: direct fp32 stores (float2 per fragment half)
#pragma unroll
    for (int mi = 0; mi < 4; mi++) {
        const int row0 = tileM + warp_m * 64 + mi * 16 + g;
#pragma unroll
        for (int nj = 0; nj < 8; nj++) {
            const int col = tileN + warp_n * 64 + nj * 8 + 2 * tig;
            float2 bv = {0.0f, 0.0f};
            if (bias) bv = *(const float2*)(bias + col);
            float2 lo = { acc[mi][nj][0] + bv.x, acc[mi][nj][1] + bv.y };
            float2 hi = { acc[mi][nj][2] + bv.x, acc[mi][nj][3] + bv.y };
            *(float2*)(C + (size_t)row0 * Nld + col)       = lo;
            *(float2*)(C + (size_t)(row0 + 8) * Nld + col) = hi;
        }
    }
}

// ---------------------------------------------------------------------------
// theta: Qe = [cos(Q*inv_wl + pb) | sin(...)], Ke likewise; tf32-rounded.
// ---------------------------------------------------------------------------
__global__ void __launch_bounds__(256)
theta_kernel(const float* __restrict__ Q, const float* __restrict__ K,
             const float* __restrict__ pb,
             float* __restrict__ Qe, float* __restrict__ Ke)
{
    const int idx = blockIdx.x * blockDim.x + threadIdx.x;
    const int d = idx & (DIM - 1);
    const int m = idx >> 10;
    const float WLC = (float)(6.283185307179586 / (double)DIM);
    float wl  = (float)(d + 1) * WLC;
    float inv = 1.0f / (wl + 1e-8f);
    float p   = pb[d];

    float sq, cq, sk, ck;
    sincosf(fmaf(Q[idx], inv, p), &sq, &cq);
    sincosf(fmaf(K[idx], inv, p), &sk, &ck);

    size_t base = (size_t)m * DE;
    Qe[base + d]        = to_tf32(cq);
    Qe[base + DIM + d]  = to_tf32(sq);
    Ke[base + d]        = to_tf32(ck);
    Ke[base + DIM + d]  = to_tf32(sk);
}

// ---------------------------------------------------------------------------
// V transpose per batch (+ tf32 rounding): Vt[b][n][s] = V[b][s][n]
// ---------------------------------------------------------------------------
__global__ void __launch_bounds__(256)
transpose_round(const float* __restrict__ V, float* __restrict__ Vt)
{
    __shared__ float t[32][33];
    const int b  = blockIdx.z;
    const int s0 = blockIdx.y * 32;
    const int n0 = blockIdx.x * 32;
    V  += (size_t)b * SEQ * DIM;
    Vt += (size_t)b * DIM * SEQ;
    const int x = threadIdx.x, y = threadIdx.y;   // 32 x 8
#pragma unroll
    for (int i = 0; i < 32; i += 8)
        t[y + i][x] = V[(size_t)(s0 + y + i) * DIM + n0 + x];
    __syncthreads();
#pragma unroll
    for (int i = 0; i < 32; i += 8)
        Vt[(size_t)(n0 + y + i) * SEQ + s0 + x] = to_tf32(t[x][y + i]);
}

// ---------------------------------------------------------------------------
// softmax rows (len SEQ), logits /32; outputs tf32-rounded weights.
// ---------------------------------------------------------------------------
__global__ void __launch_bounds__(256)
softmax_rows(float* __restrict__ S)
{
    __shared__ float sm[8];
    float* p = S + (size_t)blockIdx.x * SEQ;
    float4* p4 = (float4*)p;
    const int t    = threadIdx.x;
    const int lane = t & 31;
    const int wid  = t >> 5;
    const float SCALE = 0.03125f;

    float v[16];
    float mx = -1e30f;
#pragma unroll
    for (int i = 0; i < 4; i++) {
        float4 x = p4[t + i * 256];
        v[4*i+0] = x.x * SCALE; v[4*i+1] = x.y * SCALE;
        v[4*i+2] = x.z * SCALE; v[4*i+3] = x.w * SCALE;
        mx = fmaxf(mx, fmaxf(fmaxf(v[4*i+0], v[4*i+1]),
                             fmaxf(v[4*i+2], v[4*i+3])));
    }
#pragma unroll
    for (int off = 16; off >= 1; off >>= 1)
        mx = fmaxf(mx, __shfl_xor_sync(0xffffffffu, mx, off));
    if (lane == 0) sm[wid] = mx;
    __syncthreads();
    mx = sm[0];
#pragma unroll
    for (int w = 1; w < 8; w++) mx = fmaxf(mx, sm[w]);
    __syncthreads();

    float sum = 0.0f;
#pragma unroll
    for (int i = 0; i < 16; i++) { v[i] = expf(v[i] - mx); sum += v[i]; }
#pragma unroll
    for (int off = 16; off >= 1; off >>= 1)
        sum += __shfl_xor_sync(0xffffffffu, sum, off);
    if (lane == 0) sm[wid] = sum;
    __syncthreads();
    sum = sm[0];
#pragma unroll
    for (int w = 1; w < 8; w++) sum += sm[w];
    float inv = 1.0f / sum;

#pragma unroll
    for (int i = 0; i < 4; i++) {
        float4 o = { to_tf32(v[4*i+0]*inv), to_tf32(v[4*i+1]*inv),
                     to_tf32(v[4*i+2]*inv), to_tf32(v[4*i+3]*inv) };
        p4[t + i * 256] = o;
    }
}

// ---------------------------------------------------------------------------
extern "C" void kernel_launch(void* const* d_in, const int* in_sizes, int n_in,
                              void* d_out, int out_size)
{
    const float* x  = (const float*)d_in[0];
    const float* Wq = (const float*)d_in[1];
    const float* bq = (const float*)d_in[2];
    const float* Wk = (const float*)d_in[3];
    const float* bk = (const float*)d_in[4];
    const float* Wv = (const float*)d_in[5];
    const float* bv = (const float*)d_in[6];
    const float* pb = (const float*)d_in[7];
    float* out = (float*)d_out;

    float *Q, *K, *V, *Vt, *Qe, *Ke, *Sm;
    cudaGetSymbolAddress((void**)&Q,  g_Q);
    cudaGetSymbolAddress((void**)&K,  g_K);
    cudaGetSymbolAddress((void**)&V,  g_V);
    cudaGetSymbolAddress((void**)&Vt, g_Vt);
    cudaGetSymbolAddress((void**)&Qe, g_Qe);
    cudaGetSymbolAddress((void**)&Ke, g_Ke);
    cudaGetSymbolAddress((void**)&Sm, g_S);

    cudaFuncSetAttribute(tc_gemm<false>,
                         cudaFuncAttributeMaxDynamicSharedMemorySize,
                         GEMM_SMEM_BYTES);
    cudaFuncSetAttribute(tc_gemm<true>,
                         cudaFuncAttributeMaxDynamicSharedMemorySize,
                         GEMM_SMEM_BYTES);

    // 1) QKV projections on tensor cores.
    //    Q, K: 3xTF32 split (theta amplifies errors up to 163x -> need fp32-like)
    //    V: plain tf32 (error not amplified)
    dim3 gProj(DIM / 256, MTOT / 128, 1);
    tc_gemm<true><<<gProj, 256, GEMM_SMEM_BYTES>>>(
        x, Wq, bq, Q, DIM, DIM, 0, 0, 0);
    tc_gemm<true><<<gProj, 256, GEMM_SMEM_BYTES>>>(
        x, Wk, bk, K, DIM, DIM, 0, 0, 0);
    tc_gemm<false><<<gProj, 256, GEMM_SMEM_BYTES>>>(
        x, Wv, bv, V, DIM, DIM, 0, 0, 0);

    // 2) theta -> [cos | sin] (tf32-rounded)
    theta_kernel<<<(MTOT * DIM) / 256, 256>>>(Q, K, pb, Qe, Ke);

    // 3) V transpose (+ tf32 round) for PV tensor GEMM
    dim3 gT(DIM / 32, SEQ / 32, BATCH);
    transpose_round<<<gT, dim3(32, 8)>>>(V, Vt);

    // 4) sim = Qe @ Ke^T per batch (tf32 mma.sync)
    dim3 gSim(SEQ / 256, SEQ / 128, BATCH);
    tc_gemm<false><<<gSim, 256, GEMM_SMEM_BYTES>>>(
        Qe, Ke, nullptr, Sm, SEQ, DE,
        (size_t)SEQ * DE, (size_t)SEQ * DE, (size_t)SEQ * SEQ);

    // 5) softmax(sim / 32) rows (tf32-rounded weights)
    softmax_rows<<<BATCH * SEQ, 256>>>(Sm);

    // 6) out = weights @ Vt^T per batch (tf32 mma.sync)
    dim3 gPV(DIM / 256, SEQ / 128, BATCH);
    tc_gemm<false><<<gPV, 256, GEMM_SMEM_BYTES>>>(
        Sm, Vt, nullptr, out, DIM, SEQ,
        (size_t)SEQ * SEQ, (size_t)DIM * SEQ, (size_t)SEQ * DIM);
}

// round 6
// speedup vs baseline: 1.4078x; 1.4078x over previous
#include <cuda_runtime.h>
#include <math.h>
#include <stdint.h>

// Problem sizes (fixed)
#define BATCH 2
#define SEQ   4096
#define DIM   1024
#define MTOT  (BATCH * SEQ)     // 8192
#define DE    (2 * DIM)         // 2048  (cos || sin concatenated)

// ---------------- scratch (device globals; no allocation allowed) ----------
__device__ float g_Q [MTOT * DIM];
__device__ float g_K [MTOT * DIM];
__device__ float g_V [MTOT * DIM];
__device__ float g_Vt[MTOT * DIM];                  // V transposed per batch [DIM, SEQ]
__device__ float g_Qe[MTOT * DE];
__device__ float g_Ke[MTOT * DE];
__device__ float g_S [(size_t)BATCH * SEQ * SEQ];   // scores / weights (134 MB)

// ============================ helpers =======================================
__device__ __forceinline__ uint32_t smem_u32(const void* p) {
    uint32_t a;
    asm("{ .reg .u64 t; cvta.to.shared.u64 t, %1; cvt.u32.u64 %0, t; }"
        : "=r"(a) : "l"(p));
    return a;
}

__device__ __forceinline__ float to_tf32(float x) {
    uint32_t u;
    asm("cvt.rna.tf32.f32 %0, %1;" : "=r"(u) : "f"(x));
    return __uint_as_float(u);
}

__device__ __forceinline__ uint32_t tf32_bits(float x) {
    uint32_t u;
    asm("cvt.rna.tf32.f32 %0, %1;" : "=r"(u) : "f"(x));
    return u;
}

__device__ __forceinline__ void cpasync16(uint32_t saddr, const void* gaddr) {
    asm volatile("cp.async.cg.shared.global [%0], [%1], 16;"
                 :: "r"(saddr), "l"(gaddr) : "memory");
}

__device__ __forceinline__ void mma_tf32(float c[4], const uint32_t a[4],
                                         const uint32_t b[2]) {
    asm volatile(
        "mma.sync.aligned.m16n8k8.row.col.f32.tf32.tf32.f32 "
        "{%0,%1,%2,%3}, {%4,%5,%6,%7}, {%8,%9}, {%0,%1,%2,%3};"
        : "+f"(c[0]), "+f"(c[1]), "+f"(c[2]), "+f"(c[3])
        : "r"(a[0]), "r"(a[1]), "r"(a[2]), "r"(a[3]),
          "r"(b[0]), "r"(b[1]));
}

// ============================================================================
// tf32 tensor-core NT GEMM via mma.sync: C[M,N] = A[M,K] @ B[N,K]^T (+bias).
// PROVEN R3 CONFIG: 128x128x32 CTA tile, 3-stage cp.async pipeline, 256
// threads (8 warps, 2x4 grid, warp tile 64x32), mma.m16n8k8, rows padded to
// 36 floats (conflict-free fragment LDS). 110 KB smem -> 2 CTAs/SM possible.
// SPLIT3: 3xTF32 Karatsuba split (near-fp32) for Q/K projections.
// Requires: M%128==0, N%128==0, K%32==0. Inputs pre-rounded to tf32 when
// SPLIT3==false (split path handles raw fp32 exactly).
// ============================================================================
#define MMA_STAGE_BYTES  36864              // 2 * 128 * 36 * 4
#define MMA_SMEM_BYTES   (3 * MMA_STAGE_BYTES)

template<bool SPLIT3>
__global__ void __launch_bounds__(256, 1)
mma_nt_tf32(const float* __restrict__ A, const float* __restrict__ B,
            const float* __restrict__ bias, float* __restrict__ C,
            int Nld, int K,
            size_t strA, size_t strB, size_t strC)
{
    extern __shared__ float dynsmem[];
    const uint32_t sb = smem_u32(dynsmem);

    const int tid  = threadIdx.x;
    const int wid  = tid >> 5;
    const int lane = tid & 31;

    A += strA * blockIdx.z;
    B += strB * blockIdx.z;
    C += strC * blockIdx.z;
    const int tileM = blockIdx.y * 128;
    const int tileN = blockIdx.x * 128;

    // ---- loader mapping: thread covers rows baseRow + 32*i (i<4), 16B seg
    const int baseRow = tid >> 3;      // 0..31
    const int seg     = tid & 7;       // 0..7
    const float* Ath = A + (size_t)(tileM + baseRow) * K + seg * 4;
    const float* Bth = B + (size_t)(tileN + baseRow) * K + seg * 4;
    const uint32_t thoff = (uint32_t)(baseRow * 144 + seg * 16);

#define ISSUE_STAGE(KT, S) do {                                               \
    uint32_t _sa = sb + (uint32_t)(S) * MMA_STAGE_BYTES + thoff;              \
    const float* _ga = Ath + (size_t)(KT) * 32;                               \
    const float* _gb = Bth + (size_t)(KT) * 32;                               \
    _Pragma("unroll")                                                         \
    for (int _i = 0; _i < 4; _i++)                                            \
        cpasync16(_sa + _i * (32u * 144u), _ga + (size_t)_i * 32 * K);        \
    _Pragma("unroll")                                                         \
    for (int _i = 0; _i < 4; _i++)                                            \
        cpasync16(_sa + 18432u + _i * (32u * 144u), _gb + (size_t)_i * 32 * K); \
    asm volatile("cp.async.commit_group;" ::: "memory");                      \
} while (0)

    const int nkt = K >> 5;
    ISSUE_STAGE(0, 0);
    ISSUE_STAGE(1, 1);

    // ---- compute mapping
    const int warp_m = wid >> 2;       // 0..1  -> 64 rows
    const int warp_n = wid & 3;        // 0..3  -> 32 cols
    const int g   = lane >> 2;         // 0..7
    const int tig = lane & 3;          // 0..3

    float acc[4][4][4];
#pragma unroll
    for (int mi = 0; mi < 4; mi++)
#pragma unroll
        for (int nj = 0; nj < 4; nj++)
#pragma unroll
            for (int r = 0; r < 4; r++) acc[mi][nj][r] = 0.0f;

    int s = 0;   // stage of tile kt
    for (int kt = 0; kt < nkt; ++kt) {
        if (kt + 2 < nkt) {
            asm volatile("cp.async.wait_group 1;" ::: "memory");
        } else {
            asm volatile("cp.async.wait_group 0;" ::: "memory");
        }
        __syncthreads();

        if (kt + 2 < nkt) {
            const int s2 = (s + 2 >= 3) ? (s - 1) : (s + 2);
            ISSUE_STAGE(kt + 2, s2);
        }

        const float* sA = dynsmem + s * (MMA_STAGE_BYTES / 4);
        const float* sB = sA + 4608;

#pragma unroll
        for (int ks = 0; ks < 4; ++ks) {
            const int kk0 = ks * 8 + tig;
            if (!SPLIT3) {
                uint32_t afr[4][4];
#pragma unroll
                for (int mi = 0; mi < 4; mi++) {
                    const float* pa = sA + (size_t)(warp_m * 64 + mi * 16 + g) * 36;
                    afr[mi][0] = __float_as_uint(pa[kk0]);
                    afr[mi][1] = __float_as_uint(pa[8 * 36 + kk0]);
                    afr[mi][2] = __float_as_uint(pa[kk0 + 4]);
                    afr[mi][3] = __float_as_uint(pa[8 * 36 + kk0 + 4]);
                }
                uint32_t bfr[4][2];
#pragma unroll
                for (int nj = 0; nj < 4; nj++) {
                    const float* pb = sB + (size_t)(warp_n * 32 + nj * 8 + g) * 36;
                    bfr[nj][0] = __float_as_uint(pb[kk0]);
                    bfr[nj][1] = __float_as_uint(pb[kk0 + 4]);
                }
#pragma unroll
                for (int mi = 0; mi < 4; mi++)
#pragma unroll
                    for (int nj = 0; nj < 4; nj++)
                        mma_tf32(acc[mi][nj], afr[mi], bfr[nj]);
            } else {
                uint32_t ah[4][4], al[4][4], bh[4][2], bl[4][2];
#pragma unroll
                for (int mi = 0; mi < 4; mi++) {
                    const float* pa = sA + (size_t)(warp_m * 64 + mi * 16 + g) * 36;
                    float v0 = pa[kk0],     v1 = pa[8 * 36 + kk0];
                    float v2 = pa[kk0 + 4], v3 = pa[8 * 36 + kk0 + 4];
                    ah[mi][0] = tf32_bits(v0); al[mi][0] = tf32_bits(v0 - __uint_as_float(ah[mi][0]));
                    ah[mi][1] = tf32_bits(v1); al[mi][1] = tf32_bits(v1 - __uint_as_float(ah[mi][1]));
                    ah[mi][2] = tf32_bits(v2); al[mi][2] = tf32_bits(v2 - __uint_as_float(ah[mi][2]));
                    ah[mi][3] = tf32_bits(v3); al[mi][3] = tf32_bits(v3 - __uint_as_float(ah[mi][3]));
                }
#pragma unroll
                for (int nj = 0; nj < 4; nj++) {
                    const float* pb = sB + (size_t)(warp_n * 32 + nj * 8 + g) * 36;
                    float w0 = pb[kk0], w1 = pb[kk0 + 4];
                    bh[nj][0] = tf32_bits(w0); bl[nj][0] = tf32_bits(w0 - __uint_as_float(bh[nj][0]));
                    bh[nj][1] = tf32_bits(w1); bl[nj][1] = tf32_bits(w1 - __uint_as_float(bh[nj][1]));
                }
#pragma unroll
                for (int mi = 0; mi < 4; mi++)
#pragma unroll
                    for (int nj = 0; nj < 4; nj++) {
                        mma_tf32(acc[mi][nj], ah[mi], bl[nj]);
                        mma_tf32(acc[mi][nj], al[mi], bh[nj]);
                        mma_tf32(acc[mi][nj], ah[mi], bh[nj]);
                    }
            }
        }
        __syncthreads();
        s = (s + 1 == 3) ? 0 : (s + 1);
    }
#undef ISSUE_STAGE

    // ---- epilogue: direct fp32 stores (float2 per fragment half), +bias
#pragma unroll
    for (int mi = 0; mi < 4; mi++) {
        const int row0 = tileM + warp_m * 64 + mi * 16 + g;
#pragma unroll
        for (int nj = 0; nj < 4; nj++) {
            const int col = tileN + warp_n * 32 + nj * 8 + 2 * tig;
            float2 bv = {0.0f, 0.0f};
            if (bias) bv = *(const float2*)(bias + col);
            float2 lo = { acc[mi][nj][0] + bv.x, acc[mi][nj][1] + bv.y };
            float2 hi = { acc[mi][nj][2] + bv.x, acc[mi][nj][3] + bv.y };
            *(float2*)(C + (size_t)row0 * Nld + col)       = lo;
            *(float2*)(C + (size_t)(row0 + 8) * Nld + col) = hi;
        }
    }
}

// ---------------------------------------------------------------------------
// theta: Qe = [cos(Q*inv_wl + pb) | sin(...)], Ke likewise; tf32-rounded.
// ---------------------------------------------------------------------------
__global__ void __launch_bounds__(256)
theta_kernel(const float* __restrict__ Q, const float* __restrict__ K,
             const float* __restrict__ pb,
             float* __restrict__ Qe, float* __restrict__ Ke)
{
    const int idx = blockIdx.x * blockDim.x + threadIdx.x;
    const int d = idx & (DIM - 1);
    const int m = idx >> 10;
    const float WLC = (float)(6.283185307179586 / (double)DIM);
    float wl  = (float)(d + 1) * WLC;
    float inv = 1.0f / (wl + 1e-8f);
    float p   = pb[d];

    float sq, cq, sk, ck;
    sincosf(fmaf(Q[idx], inv, p), &sq, &cq);
    sincosf(fmaf(K[idx], inv, p), &sk, &ck);

    size_t base = (size_t)m * DE;
    Qe[base + d]        = to_tf32(cq);
    Qe[base + DIM + d]  = to_tf32(sq);
    Ke[base + d]        = to_tf32(ck);
    Ke[base + DIM + d]  = to_tf32(sk);
}

// ---------------------------------------------------------------------------
// V transpose per batch (+ tf32 rounding): Vt[b][n][s] = V[b][s][n]
// ---------------------------------------------------------------------------
__global__ void __launch_bounds__(256)
transpose_round(const float* __restrict__ V, float* __restrict__ Vt)
{
    __shared__ float t[32][33];
    const int b  = blockIdx.z;
    const int s0 = blockIdx.y * 32;
    const int n0 = blockIdx.x * 32;
    V  += (size_t)b * SEQ * DIM;
    Vt += (size_t)b * DIM * SEQ;
    const int x = threadIdx.x, y = threadIdx.y;   // 32 x 8
#pragma unroll
    for (int i = 0; i < 32; i += 8)
        t[y + i][x] = V[(size_t)(s0 + y + i) * DIM + n0 + x];
    __syncthreads();
#pragma unroll
    for (int i = 0; i < 32; i += 8)
        Vt[(size_t)(n0 + y + i) * SEQ + s0 + x] = to_tf32(t[x][y + i]);
}

// ---------------------------------------------------------------------------
// softmax rows (len SEQ), logits /32; outputs tf32-rounded weights.
// ---------------------------------------------------------------------------
__global__ void __launch_bounds__(256)
softmax_rows(float* __restrict__ S)
{
    __shared__ float sm[8];
    float* p = S + (size_t)blockIdx.x * SEQ;
    float4* p4 = (float4*)p;
    const int t    = threadIdx.x;
    const int lane = t & 31;
    const int wid  = t >> 5;
    const float SCALE = 0.03125f;

    float v[16];
    float mx = -1e30f;
#pragma unroll
    for (int i = 0; i < 4; i++) {
        float4 x = p4[t + i * 256];
        v[4*i+0] = x.x * SCALE; v[4*i+1] = x.y * SCALE;
        v[4*i+2] = x.z * SCALE; v[4*i+3] = x.w * SCALE;
        mx = fmaxf(mx, fmaxf(fmaxf(v[4*i+0], v[4*i+1]),
                             fmaxf(v[4*i+2], v[4*i+3])));
    }
#pragma unroll
    for (int off = 16; off >= 1; off >>= 1)
        mx = fmaxf(mx, __shfl_xor_sync(0xffffffffu, mx, off));
    if (lane == 0) sm[wid] = mx;
    __syncthreads();
    mx = sm[0];
#pragma unroll
    for (int w = 1; w < 8; w++) mx = fmaxf(mx, sm[w]);
    __syncthreads();

    float sum = 0.0f;
#pragma unroll
    for (int i = 0; i < 16; i++) { v[i] = expf(v[i] - mx); sum += v[i]; }
#pragma unroll
    for (int off = 16; off >= 1; off >>= 1)
        sum += __shfl_xor_sync(0xffffffffu, sum, off);
    if (lane == 0) sm[wid] = sum;
    __syncthreads();
    sum = sm[0];
#pragma unroll
    for (int w = 1; w < 8; w++) sum += sm[w];
    float inv = 1.0f / sum;

#pragma unroll
    for (int i = 0; i < 4; i++) {
        float4 o = { to_tf32(v[4*i+0]*inv), to_tf32(v[4*i+1]*inv),
                     to_tf32(v[4*i+2]*inv), to_tf32(v[4*i+3]*inv) };
        p4[t + i * 256] = o;
    }
}

// ---------------------------------------------------------------------------
extern "C" void kernel_launch(void* const* d_in, const int* in_sizes, int n_in,
                              void* d_out, int out_size)
{
    const float* x  = (const float*)d_in[0];
    const float* Wq = (const float*)d_in[1];
    const float* bq = (const float*)d_in[2];
    const float* Wk = (const float*)d_in[3];
    const float* bk = (const float*)d_in[4];
    const float* Wv = (const float*)d_in[5];
    const float* bv = (const float*)d_in[6];
    const float* pb = (const float*)d_in[7];
    float* out = (float*)d_out;

    float *Q, *K, *V, *Vt, *Qe, *Ke, *Sm;
    cudaGetSymbolAddress((void**)&Q,  g_Q);
    cudaGetSymbolAddress((void**)&K,  g_K);
    cudaGetSymbolAddress((void**)&V,  g_V);
    cudaGetSymbolAddress((void**)&Vt, g_Vt);
    cudaGetSymbolAddress((void**)&Qe, g_Qe);
    cudaGetSymbolAddress((void**)&Ke, g_Ke);
    cudaGetSymbolAddress((void**)&Sm, g_S);

    cudaFuncSetAttribute(mma_nt_tf32<false>,
                         cudaFuncAttributeMaxDynamicSharedMemorySize,
                         MMA_SMEM_BYTES);
    cudaFuncSetAttribute(mma_nt_tf32<true>,
                         cudaFuncAttributeMaxDynamicSharedMemorySize,
                         MMA_SMEM_BYTES);

    // 1) QKV projections on tensor cores (proven 128x128 config).
    //    Q, K: 3xTF32 split (theta amplifies errors up to 163x).
    //    V: plain tf32 (error not amplified through softmax weights).
    dim3 gProj(DIM / 128, MTOT / 128, 1);
    mma_nt_tf32<true><<<gProj, 256, MMA_SMEM_BYTES>>>(
        x, Wq, bq, Q, DIM, DIM, 0, 0, 0);
    mma_nt_tf32<true><<<gProj, 256, MMA_SMEM_BYTES>>>(
        x, Wk, bk, K, DIM, DIM, 0, 0, 0);
    mma_nt_tf32<false><<<gProj, 256, MMA_SMEM_BYTES>>>(
        x, Wv, bv, V, DIM, DIM, 0, 0, 0);

    // 2) theta -> [cos | sin] (tf32-rounded)
    theta_kernel<<<(MTOT * DIM) / 256, 256>>>(Q, K, pb, Qe, Ke);

    // 3) V transpose (+ tf32 round) for PV tensor GEMM
    dim3 gT(DIM / 32, SEQ / 32, BATCH);
    transpose_round<<<gT, dim3(32, 8)>>>(V, Vt);

    // 4) sim = Qe @ Ke^T per batch (tf32 mma.sync)
    dim3 gSim(SEQ / 128, SEQ / 128, BATCH);
    mma_nt_tf32<false><<<gSim, 256, MMA_SMEM_BYTES>>>(
        Qe, Ke, nullptr, Sm, SEQ, DE,
        (size_t)SEQ * DE, (size_t)SEQ * DE, (size_t)SEQ * SEQ);

    // 5) softmax(sim / 32) rows (tf32-rounded weights)
    softmax_rows<<<BATCH * SEQ, 256>>>(Sm);

    // 6) out = weights @ Vt^T per batch (tf32 mma.sync)
    dim3 gPV(DIM / 128, SEQ / 128, BATCH);
    mma_nt_tf32<false><<<gPV, 256, MMA_SMEM_BYTES>>>(
        Sm, Vt, nullptr, out, DIM, SEQ,
        (size_t)SEQ * SEQ, (size_t)DIM * SEQ, (size_t)SEQ * DIM);
}

// round 7
// speedup vs baseline: 1.4585x; 1.0360x over previous
#include <cuda_runtime.h>
#include <math.h>
#include <stdint.h>

// Problem sizes (fixed)
#define BATCH 2
#define SEQ   4096
#define DIM   1024
#define MTOT  (BATCH * SEQ)     // 8192
#define DE    (2 * DIM)         // 2048  (cos || sin concatenated)

// ---------------- scratch (device globals; no allocation allowed) ----------
__device__ float g_Q [MTOT * DIM];
__device__ float g_K [MTOT * DIM];
__device__ float g_V [MTOT * DIM];
__device__ float g_Vt[MTOT * DIM];                  // V transposed per batch [DIM, SEQ]
__device__ float g_Qe[MTOT * DE];
__device__ float g_Ke[MTOT * DE];
__device__ float g_S [(size_t)BATCH * SEQ * SEQ];   // scores / weights (134 MB)

// ============================ helpers =======================================
__device__ __forceinline__ uint32_t smem_u32(const void* p) {
    uint32_t a;
    asm("{ .reg .u64 t; cvta.to.shared.u64 t, %1; cvt.u32.u64 %0, t; }"
        : "=r"(a) : "l"(p));
    return a;
}

__device__ __forceinline__ float to_tf32(float x) {
    uint32_t u;
    asm("cvt.rna.tf32.f32 %0, %1;" : "=r"(u) : "f"(x));
    return __uint_as_float(u);
}

__device__ __forceinline__ uint32_t tf32_bits(float x) {
    uint32_t u;
    asm("cvt.rna.tf32.f32 %0, %1;" : "=r"(u) : "f"(x));
    return u;
}

__device__ __forceinline__ uint32_t rna_bits_u(uint32_t v) {
    uint32_t u;
    asm("cvt.rna.tf32.f32 %0, %1;" : "=r"(u) : "f"(__uint_as_float(v)));
    return u;
}

__device__ __forceinline__ void cpasync16(uint32_t saddr, const void* gaddr) {
    asm volatile("cp.async.cg.shared.global [%0], [%1], 16;"
                 :: "r"(saddr), "l"(gaddr) : "memory");
}

__device__ __forceinline__ void ldsm_x4(uint32_t r[4], uint32_t addr) {
    asm volatile("ldmatrix.sync.aligned.m8n8.x4.shared.b16 {%0,%1,%2,%3}, [%4];"
                 : "=r"(r[0]), "=r"(r[1]), "=r"(r[2]), "=r"(r[3])
                 : "r"(addr));
}

__device__ __forceinline__ void mma_tf32(float c[4], const uint32_t a[4],
                                         const uint32_t b[2]) {
    asm volatile(
        "mma.sync.aligned.m16n8k8.row.col.f32.tf32.tf32.f32 "
        "{%0,%1,%2,%3}, {%4,%5,%6,%7}, {%8,%9}, {%0,%1,%2,%3};"
        : "+f"(c[0]), "+f"(c[1]), "+f"(c[2]), "+f"(c[3])
        : "r"(a[0]), "r"(a[1]), "r"(a[2]), "r"(a[3]),
          "r"(b[0]), "r"(b[1]));
}

// Rounding / accuracy modes for the GEMM
#define MODE_RAW    0   // pass fp32 bits straight to mma (HW truncates; use for pre-rounded inputs)
#define MODE_RNA    1   // round-to-nearest tf32 on loaded fragments (unbiased single-pass)
#define MODE_SPLIT3 2   // 3xTF32 Karatsuba split (near-fp32; for Q/K projections)

// ============================================================================
// tf32 tensor-core NT GEMM via mma.sync: C[M,N] = A[M,K] @ B[N,K]^T (+bias).
// 128x128x32 CTA tile, 3-stage cp.async pipeline, 256 threads (8 warps,
// 2x4 grid, warp tile 64x32), mma.m16n8k8, rows padded to 36 floats.
// Fragment loads via ldmatrix.m8n8.x4 (4x fewer issue slots than scalar LDS;
// conflict-free: row stride 144B -> 8 rows x 4 banks = all 32 banks).
// 110 KB smem -> 2 CTAs/SM. Requires M%128==0, N%128==0, K%32==0.
// ============================================================================
#define MMA_STAGE_BYTES  36864              // 2 * 128 * 36 * 4
#define MMA_SMEM_BYTES   (3 * MMA_STAGE_BYTES)

template<int MODE>
__global__ void __launch_bounds__(256, 1)
mma_nt_tf32(const float* __restrict__ A, const float* __restrict__ B,
            const float* __restrict__ bias, float* __restrict__ C,
            int Nld, int K,
            size_t strA, size_t strB, size_t strC)
{
    extern __shared__ float dynsmem[];
    const uint32_t sb = smem_u32(dynsmem);

    const int tid  = threadIdx.x;
    const int wid  = tid >> 5;
    const int lane = tid & 31;

    A += strA * blockIdx.z;
    B += strB * blockIdx.z;
    C += strC * blockIdx.z;
    const int tileM = blockIdx.y * 128;
    const int tileN = blockIdx.x * 128;

    // ---- loader mapping: thread covers rows baseRow + 32*i (i<4), 16B seg
    const int baseRow = tid >> 3;      // 0..31
    const int seg     = tid & 7;       // 0..7
    const float* Ath = A + (size_t)(tileM + baseRow) * K + seg * 4;
    const float* Bth = B + (size_t)(tileN + baseRow) * K + seg * 4;
    const uint32_t thoff = (uint32_t)(baseRow * 144 + seg * 16);

#define ISSUE_STAGE(KT, S) do {                                               \
    uint32_t _sa = sb + (uint32_t)(S) * MMA_STAGE_BYTES + thoff;              \
    const float* _ga = Ath + (size_t)(KT) * 32;                               \
    const float* _gb = Bth + (size_t)(KT) * 32;                               \
    _Pragma("unroll")                                                         \
    for (int _i = 0; _i < 4; _i++)                                            \
        cpasync16(_sa + _i * (32u * 144u), _ga + (size_t)_i * 32 * K);        \
    _Pragma("unroll")                                                         \
    for (int _i = 0; _i < 4; _i++)                                            \
        cpasync16(_sa + 18432u + _i * (32u * 144u), _gb + (size_t)_i * 32 * K); \
    asm volatile("cp.async.commit_group;" ::: "memory");                      \
} while (0)

    const int nkt = K >> 5;
    ISSUE_STAGE(0, 0);
    ISSUE_STAGE(1, 1);

    // ---- compute mapping
    const int warp_m = wid >> 2;       // 0..1  -> 64 rows
    const int warp_n = wid & 3;        // 0..3  -> 32 cols
    const int g   = lane >> 2;         // 0..7
    const int tig = lane & 3;          // 0..3

    // ldmatrix lane-address components (bytes):
    // A x4: m0 = rows 0-7 @k, m1 = rows 8-15 @k, m2 = rows 0-7 @k+4, m3 = rows 8-15 @k+4
    const uint32_t laneA = (uint32_t)((lane & 15) * 144 + (lane >> 4) * 16);
    // B x4 (nj pair): m0 = nj rows @k, m1 = nj rows @k+4, m2 = nj+1 rows @k, m3 = nj+1 rows @k+4
    const uint32_t laneB = (uint32_t)(((lane & 7) + ((lane >> 4) & 1) * 8) * 144
                                      + ((lane >> 3) & 1) * 16);

    float acc[4][4][4];
#pragma unroll
    for (int mi = 0; mi < 4; mi++)
#pragma unroll
        for (int nj = 0; nj < 4; nj++)
#pragma unroll
            for (int r = 0; r < 4; r++) acc[mi][nj][r] = 0.0f;

    int s = 0;   // stage of tile kt
    for (int kt = 0; kt < nkt; ++kt) {
        if (kt + 2 < nkt) {
            asm volatile("cp.async.wait_group 1;" ::: "memory");
        } else {
            asm volatile("cp.async.wait_group 0;" ::: "memory");
        }
        __syncthreads();

        if (kt + 2 < nkt) {
            const int s2 = (s + 2 >= 3) ? (s - 1) : (s + 2);
            ISSUE_STAGE(kt + 2, s2);
        }

        const uint32_t sAaddr = sb + (uint32_t)s * MMA_STAGE_BYTES;
        const uint32_t aBase = sAaddr + (uint32_t)(warp_m * 64) * 144 + laneA;
        const uint32_t bBase = sAaddr + 18432u + (uint32_t)(warp_n * 32) * 144 + laneB;

#pragma unroll
        for (int ks = 0; ks < 4; ++ks) {
            uint32_t afr[4][4];
            uint32_t bfr[4][2];
            {
                uint32_t t0[4], t1[4];
#pragma unroll
                for (int mi = 0; mi < 4; mi++)
                    ldsm_x4(afr[mi], aBase + mi * 2304u + ks * 32u);
                ldsm_x4(t0, bBase + ks * 32u);            // nj 0,1
                ldsm_x4(t1, bBase + 2304u + ks * 32u);    // nj 2,3
                bfr[0][0] = t0[0]; bfr[0][1] = t0[1];
                bfr[1][0] = t0[2]; bfr[1][1] = t0[3];
                bfr[2][0] = t1[0]; bfr[2][1] = t1[1];
                bfr[3][0] = t1[2]; bfr[3][1] = t1[3];
            }

            if (MODE == MODE_RAW) {
#pragma unroll
                for (int mi = 0; mi < 4; mi++)
#pragma unroll
                    for (int nj = 0; nj < 4; nj++)
                        mma_tf32(acc[mi][nj], afr[mi], bfr[nj]);
            } else if (MODE == MODE_RNA) {
#pragma unroll
                for (int mi = 0; mi < 4; mi++)
#pragma unroll
                    for (int r = 0; r < 4; r++)
                        afr[mi][r] = rna_bits_u(afr[mi][r]);
#pragma unroll
                for (int nj = 0; nj < 4; nj++) {
                    bfr[nj][0] = rna_bits_u(bfr[nj][0]);
                    bfr[nj][1] = rna_bits_u(bfr[nj][1]);
                }
#pragma unroll
                for (int mi = 0; mi < 4; mi++)
#pragma unroll
                    for (int nj = 0; nj < 4; nj++)
                        mma_tf32(acc[mi][nj], afr[mi], bfr[nj]);
            } else {   // MODE_SPLIT3
                uint32_t ah[4][4], al[4][4], bh[4][2], bl[4][2];
#pragma unroll
                for (int mi = 0; mi < 4; mi++)
#pragma unroll
                    for (int r = 0; r < 4; r++) {
                        float v = __uint_as_float(afr[mi][r]);
                        ah[mi][r] = tf32_bits(v);
                        al[mi][r] = tf32_bits(v - __uint_as_float(ah[mi][r]));
                    }
#pragma unroll
                for (int nj = 0; nj < 4; nj++)
#pragma unroll
                    for (int r = 0; r < 2; r++) {
                        float w = __uint_as_float(bfr[nj][r]);
                        bh[nj][r] = tf32_bits(w);
                        bl[nj][r] = tf32_bits(w - __uint_as_float(bh[nj][r]));
                    }
#pragma unroll
                for (int mi = 0; mi < 4; mi++)
#pragma unroll
                    for (int nj = 0; nj < 4; nj++) {
                        mma_tf32(acc[mi][nj], ah[mi], bl[nj]);
                        mma_tf32(acc[mi][nj], al[mi], bh[nj]);
                        mma_tf32(acc[mi][nj], ah[mi], bh[nj]);
                    }
            }
        }
        __syncthreads();
        s = (s + 1 == 3) ? 0 : (s + 1);
    }
#undef ISSUE_STAGE

    // ---- epilogue: direct fp32 stores (float2 per fragment half), +bias
#pragma unroll
    for (int mi = 0; mi < 4; mi++) {
        const int row0 = tileM + warp_m * 64 + mi * 16 + g;
#pragma unroll
        for (int nj = 0; nj < 4; nj++) {
            const int col = tileN + warp_n * 32 + nj * 8 + 2 * tig;
            float2 bv = {0.0f, 0.0f};
            if (bias) bv = *(const float2*)(bias + col);
            float2 lo = { acc[mi][nj][0] + bv.x, acc[mi][nj][1] + bv.y };
            float2 hi = { acc[mi][nj][2] + bv.x, acc[mi][nj][3] + bv.y };
            *(float2*)(C + (size_t)row0 * Nld + col)       = lo;
            *(float2*)(C + (size_t)(row0 + 8) * Nld + col) = hi;
        }
    }
}

// ---------------------------------------------------------------------------
// theta: Qe = [cos(Q*inv_wl + pb) | sin(...)], Ke likewise; tf32-rounded.
// ---------------------------------------------------------------------------
__global__ void __launch_bounds__(256)
theta_kernel(const float* __restrict__ Q, const float* __restrict__ K,
             const float* __restrict__ pb,
             float* __restrict__ Qe, float* __restrict__ Ke)
{
    const int idx = blockIdx.x * blockDim.x + threadIdx.x;
    const int d = idx & (DIM - 1);
    const int m = idx >> 10;
    const float WLC = (float)(6.283185307179586 / (double)DIM);
    float wl  = (float)(d + 1) * WLC;
    float inv = 1.0f / (wl + 1e-8f);
    float p   = pb[d];

    float sq, cq, sk, ck;
    sincosf(fmaf(Q[idx], inv, p), &sq, &cq);
    sincosf(fmaf(K[idx], inv, p), &sk, &ck);

    size_t base = (size_t)m * DE;
    Qe[base + d]        = to_tf32(cq);
    Qe[base + DIM + d]  = to_tf32(sq);
    Ke[base + d]        = to_tf32(ck);
    Ke[base + DIM + d]  = to_tf32(sk);
}

// ---------------------------------------------------------------------------
// V transpose per batch (+ tf32 rounding): Vt[b][n][s] = V[b][s][n]
// ---------------------------------------------------------------------------
__global__ void __launch_bounds__(256)
transpose_round(const float* __restrict__ V, float* __restrict__ Vt)
{
    __shared__ float t[32][33];
    const int b  = blockIdx.z;
    const int s0 = blockIdx.y * 32;
    const int n0 = blockIdx.x * 32;
    V  += (size_t)b * SEQ * DIM;
    Vt += (size_t)b * DIM * SEQ;
    const int x = threadIdx.x, y = threadIdx.y;   // 32 x 8
#pragma unroll
    for (int i = 0; i < 32; i += 8)
        t[y + i][x] = V[(size_t)(s0 + y + i) * DIM + n0 + x];
    __syncthreads();
#pragma unroll
    for (int i = 0; i < 32; i += 8)
        Vt[(size_t)(n0 + y + i) * SEQ + s0 + x] = to_tf32(t[x][y + i]);
}

// ---------------------------------------------------------------------------
// softmax rows (len SEQ), logits /32; outputs tf32-rounded weights.
// ---------------------------------------------------------------------------
__global__ void __launch_bounds__(256)
softmax_rows(float* __restrict__ S)
{
    __shared__ float sm[8];
    float* p = S + (size_t)blockIdx.x * SEQ;
    float4* p4 = (float4*)p;
    const int t    = threadIdx.x;
    const int lane = t & 31;
    const int wid  = t >> 5;
    const float SCALE = 0.03125f;

    float v[16];
    float mx = -1e30f;
#pragma unroll
    for (int i = 0; i < 4; i++) {
        float4 x = p4[t + i * 256];
        v[4*i+0] = x.x * SCALE; v[4*i+1] = x.y * SCALE;
        v[4*i+2] = x.z * SCALE; v[4*i+3] = x.w * SCALE;
        mx = fmaxf(mx, fmaxf(fmaxf(v[4*i+0], v[4*i+1]),
                             fmaxf(v[4*i+2], v[4*i+3])));
    }
#pragma unroll
    for (int off = 16; off >= 1; off >>= 1)
        mx = fmaxf(mx, __shfl_xor_sync(0xffffffffu, mx, off));
    if (lane == 0) sm[wid] = mx;
    __syncthreads();
    mx = sm[0];
#pragma unroll
    for (int w = 1; w < 8; w++) mx = fmaxf(mx, sm[w]);
    __syncthreads();

    float sum = 0.0f;
#pragma unroll
    for (int i = 0; i < 16; i++) { v[i] = expf(v[i] - mx); sum += v[i]; }
#pragma unroll
    for (int off = 16; off >= 1; off >>= 1)
        sum += __shfl_xor_sync(0xffffffffu, sum, off);
    if (lane == 0) sm[wid] = sum;
    __syncthreads();
    sum = sm[0];
#pragma unroll
    for (int w = 1; w < 8; w++) sum += sm[w];
    float inv = 1.0f / sum;

#pragma unroll
    for (int i = 0; i < 4; i++) {
        float4 o = { to_tf32(v[4*i+0]*inv), to_tf32(v[4*i+1]*inv),
                     to_tf32(v[4*i+2]*inv), to_tf32(v[4*i+3]*inv) };
        p4[t + i * 256] = o;
    }
}

// ---------------------------------------------------------------------------
extern "C" void kernel_launch(void* const* d_in, const int* in_sizes, int n_in,
                              void* d_out, int out_size)
{
    const float* x  = (const float*)d_in[0];
    const float* Wq = (const float*)d_in[1];
    const float* bq = (const float*)d_in[2];
    const float* Wk = (const float*)d_in[3];
    const float* bk = (const float*)d_in[4];
    const float* Wv = (const float*)d_in[5];
    const float* bv = (const float*)d_in[6];
    const float* pb = (const float*)d_in[7];
    float* out = (float*)d_out;

    float *Q, *K, *V, *Vt, *Qe, *Ke, *Sm;
    cudaGetSymbolAddress((void**)&Q,  g_Q);
    cudaGetSymbolAddress((void**)&K,  g_K);
    cudaGetSymbolAddress((void**)&V,  g_V);
    cudaGetSymbolAddress((void**)&Vt, g_Vt);
    cudaGetSymbolAddress((void**)&Qe, g_Qe);
    cudaGetSymbolAddress((void**)&Ke, g_Ke);
    cudaGetSymbolAddress((void**)&Sm, g_S);

    cudaFuncSetAttribute(mma_nt_tf32<MODE_RAW>,
                         cudaFuncAttributeMaxDynamicSharedMemorySize,
                         MMA_SMEM_BYTES);
    cudaFuncSetAttribute(mma_nt_tf32<MODE_RNA>,
                         cudaFuncAttributeMaxDynamicSharedMemorySize,
                         MMA_SMEM_BYTES);
    cudaFuncSetAttribute(mma_nt_tf32<MODE_SPLIT3>,
                         cudaFuncAttributeMaxDynamicSharedMemorySize,
                         MMA_SMEM_BYTES);

    // 1) QKV projections on tensor cores.
    //    Q, K: 3xTF32 split (theta amplifies errors up to 163x).
    //    V: plain tf32 with explicit RNA rounding (kills truncation bias).
    dim3 gProj(DIM / 128, MTOT / 128, 1);
    mma_nt_tf32<MODE_SPLIT3><<<gProj, 256, MMA_SMEM_BYTES>>>(
        x, Wq, bq, Q, DIM, DIM, 0, 0, 0);
    mma_nt_tf32<MODE_SPLIT3><<<gProj, 256, MMA_SMEM_BYTES>>>(
        x, Wk, bk, K, DIM, DIM, 0, 0, 0);
    mma_nt_tf32<MODE_RNA><<<gProj, 256, MMA_SMEM_BYTES>>>(
        x, Wv, bv, V, DIM, DIM, 0, 0, 0);

    // 2) theta -> [cos | sin] (tf32-rounded)
    theta_kernel<<<(MTOT * DIM) / 256, 256>>>(Q, K, pb, Qe, Ke);

    // 3) V transpose (+ tf32 round) for PV tensor GEMM
    dim3 gT(DIM / 32, SEQ / 32, BATCH);
    transpose_round<<<gT, dim3(32, 8)>>>(V, Vt);

    // 4) sim = Qe @ Ke^T per batch (tf32 mma.sync; inputs pre-rounded)
    dim3 gSim(SEQ / 128, SEQ / 128, BATCH);
    mma_nt_tf32<MODE_RAW><<<gSim, 256, MMA_SMEM_BYTES>>>(
        Qe, Ke, nullptr, Sm, SEQ, DE,
        (size_t)SEQ * DE, (size_t)SEQ * DE, (size_t)SEQ * SEQ);

    // 5) softmax(sim / 32) rows (tf32-rounded weights)
    softmax_rows<<<BATCH * SEQ, 256>>>(Sm);

    // 6) out = weights @ Vt^T per batch (tf32 mma.sync; inputs pre-rounded)
    dim3 gPV(DIM / 128, SEQ / 128, BATCH);
    mma_nt_tf32<MODE_RAW><<<gPV, 256, MMA_SMEM_BYTES>>>(
        Sm, Vt, nullptr, out, DIM, SEQ,
        (size_t)SEQ * SEQ, (size_t)DIM * SEQ, (size_t)SEQ * DIM);
}

// round 8
// speedup vs baseline: 2.4293x; 1.6656x over previous
#include <cuda_runtime.h>
#include <cuda_fp16.h>
#include <math.h>
#include <stdint.h>

// Problem sizes (fixed)
#define BATCH 2
#define SEQ   4096
#define DIM   1024
#define MTOT  (BATCH * SEQ)     // 8192
#define DE    (2 * DIM)         // 2048  (cos || sin concatenated)
#define NQKV  (3 * DIM)         // 3072

// ---------------- scratch (device globals; no allocation allowed) ----------
__device__ __half g_Ax [(size_t)MTOT * NQKV];          // [8192][3072] = [xh|xh|xl]
__device__ __half g_Bw [(size_t)NQKV * NQKV];          // [3072][3072] rows: [Wh|Wl|Wh]
__device__ float  g_bias3[NQKV];
__device__ float  g_QKV[(size_t)MTOT * NQKV];          // [8192][3072] = [Q|K|V] fp32
__device__ __half g_Qe[(size_t)MTOT * DE];             // [8192][2048] = [cos|sin]
__device__ __half g_Ke[(size_t)MTOT * DE];
__device__ __half g_Vt[(size_t)MTOT * DIM];            // per batch [DIM][SEQ]
__device__ float  g_S [(size_t)BATCH * SEQ * SEQ];     // scores fp32 (134 MB)
__device__ __half g_P [(size_t)BATCH * SEQ * SEQ];     // weights fp16 (67 MB)

// ============================ helpers =======================================
__device__ __forceinline__ uint32_t smem_u32(const void* p) {
    uint32_t a;
    asm("{ .reg .u64 t; cvta.to.shared.u64 t, %1; cvt.u32.u64 %0, t; }"
        : "=r"(a) : "l"(p));
    return a;
}

__device__ __forceinline__ void cpasync16(uint32_t saddr, const void* gaddr) {
    asm volatile("cp.async.cg.shared.global [%0], [%1], 16;"
                 :: "r"(saddr), "l"(gaddr) : "memory");
}

__device__ __forceinline__ void ldsm_x4(uint32_t r[4], uint32_t addr) {
    asm volatile("ldmatrix.sync.aligned.m8n8.x4.shared.b16 {%0,%1,%2,%3}, [%4];"
                 : "=r"(r[0]), "=r"(r[1]), "=r"(r[2]), "=r"(r[3])
                 : "r"(addr));
}

__device__ __forceinline__ void mma_f16(float c[4], const uint32_t a[4],
                                        const uint32_t b[2]) {
    asm volatile(
        "mma.sync.aligned.m16n8k16.row.col.f32.f16.f16.f32 "
        "{%0,%1,%2,%3}, {%4,%5,%6,%7}, {%8,%9}, {%0,%1,%2,%3};"
        : "+f"(c[0]), "+f"(c[1]), "+f"(c[2]), "+f"(c[3])
        : "r"(a[0]), "r"(a[1]), "r"(a[2]), "r"(a[3]),
          "r"(b[0]), "r"(b[1]));
}

// ============================================================================
// fp16 tensor-core NT GEMM via mma.sync.m16n8k16:
//   C[M,N] = A[M,K] @ B[N,K]^T (+bias), fp32 accumulate/output.
// Proven R7 skeleton: 128x128 CTA tile (k-tile = 64 halfs = 128B/row),
// 3-stage cp.async ring, 256 threads (8 warps, 2x4, warp tile 64x32),
// rows padded to 144B (36 words: 8 rows x 4-bank groups = conflict-free
// ldmatrix). 110 KB smem -> 2 CTAs/SM. M%128==0, N%128==0, K%64==0.
// ============================================================================
#define H_STAGE_BYTES  36864              // 2 * 128 rows * 144 B
#define H_SMEM_BYTES   (3 * H_STAGE_BYTES)

__global__ void __launch_bounds__(256, 1)
hgemm_nt(const __half* __restrict__ A, const __half* __restrict__ B,
         const float* __restrict__ bias, float* __restrict__ C,
         int Nld, int K,
         size_t strA, size_t strB, size_t strC)
{
    extern __shared__ float dynsmem[];
    const uint32_t sb = smem_u32(dynsmem);

    const int tid  = threadIdx.x;
    const int wid  = tid >> 5;
    const int lane = tid & 31;

    A += strA * blockIdx.z;
    B += strB * blockIdx.z;
    C += strC * blockIdx.z;
    const int tileM = blockIdx.y * 128;
    const int tileN = blockIdx.x * 128;

    // ---- loader: thread covers rows baseRow + 32*i (i<4), 16B seg of 128B row
    const int baseRow = tid >> 3;      // 0..31
    const int seg     = tid & 7;       // 0..7
    const __half* Ath = A + (size_t)(tileM + baseRow) * K + seg * 8;
    const __half* Bth = B + (size_t)(tileN + baseRow) * K + seg * 8;
    const uint32_t thoff = (uint32_t)(baseRow * 144 + seg * 16);

#define ISSUE_STAGE(KT, S) do {                                               \
    uint32_t _sa = sb + (uint32_t)(S) * H_STAGE_BYTES + thoff;                \
    const __half* _ga = Ath + (size_t)(KT) * 64;                              \
    const __half* _gb = Bth + (size_t)(KT) * 64;                              \
    _Pragma("unroll")                                                         \
    for (int _i = 0; _i < 4; _i++)                                            \
        cpasync16(_sa + _i * (32u * 144u), _ga + (size_t)_i * 32 * K);        \
    _Pragma("unroll")                                                         \
    for (int _i = 0; _i < 4; _i++)                                            \
        cpasync16(_sa + 18432u + _i * (32u * 144u), _gb + (size_t)_i * 32 * K); \
    asm volatile("cp.async.commit_group;" ::: "memory");                      \
} while (0)

    const int nkt = K >> 6;            // 64 halfs per k-tile
    ISSUE_STAGE(0, 0);
    ISSUE_STAGE(1, 1);

    // ---- compute mapping
    const int warp_m = wid >> 2;       // 0..1  -> 64 rows
    const int warp_n = wid & 3;        // 0..3  -> 32 cols
    const int g   = lane >> 2;         // 0..7
    const int tig = lane & 3;          // 0..3

    // ldmatrix lane addresses (bytes), identical structure to R7 (byte-equal):
    // A x4: m0 rows0-7 @k0-7, m1 rows8-15 @k0-7, m2 rows0-7 @k8-15, m3 rows8-15 @k8-15
    const uint32_t laneA = (uint32_t)((lane & 15) * 144 + (lane >> 4) * 16);
    // B x4 (nj pair): m0 nj rows @k0-7, m1 nj @k8-15, m2 nj+1 @k0-7, m3 nj+1 @k8-15
    const uint32_t laneB = (uint32_t)(((lane & 7) + ((lane >> 4) & 1) * 8) * 144
                                      + ((lane >> 3) & 1) * 16);

    float acc[4][4][4];
#pragma unroll
    for (int mi = 0; mi < 4; mi++)
#pragma unroll
        for (int nj = 0; nj < 4; nj++)
#pragma unroll
            for (int r = 0; r < 4; r++) acc[mi][nj][r] = 0.0f;

    int s = 0;   // stage of tile kt
    for (int kt = 0; kt < nkt; ++kt) {
        if (kt + 2 < nkt) {
            asm volatile("cp.async.wait_group 1;" ::: "memory");
        } else {
            asm volatile("cp.async.wait_group 0;" ::: "memory");
        }
        __syncthreads();

        if (kt + 2 < nkt) {
            const int s2 = (s + 2 >= 3) ? (s - 1) : (s + 2);
            ISSUE_STAGE(kt + 2, s2);
        }

        const uint32_t stAddr = sb + (uint32_t)s * H_STAGE_BYTES;
        const uint32_t aBase = stAddr + (uint32_t)(warp_m * 64) * 144 + laneA;
        const uint32_t bBase = stAddr + 18432u + (uint32_t)(warp_n * 32) * 144 + laneB;

#pragma unroll
        for (int ks = 0; ks < 4; ++ks) {        // 4 x k16 per 64-half tile
            uint32_t afr[4][4];
            uint32_t bfr[4][2];
            {
                uint32_t t0[4], t1[4];
#pragma unroll
                for (int mi = 0; mi < 4; mi++)
                    ldsm_x4(afr[mi], aBase + mi * 2304u + ks * 32u);
                ldsm_x4(t0, bBase + ks * 32u);            // nj 0,1
                ldsm_x4(t1, bBase + 2304u + ks * 32u);    // nj 2,3
                bfr[0][0] = t0[0]; bfr[0][1] = t0[1];
                bfr[1][0] = t0[2]; bfr[1][1] = t0[3];
                bfr[2][0] = t1[0]; bfr[2][1] = t1[1];
                bfr[3][0] = t1[2]; bfr[3][1] = t1[3];
            }
#pragma unroll
            for (int mi = 0; mi < 4; mi++)
#pragma unroll
                for (int nj = 0; nj < 4; nj++)
                    mma_f16(acc[mi][nj], afr[mi], bfr[nj]);
        }
        __syncthreads();
        s = (s + 1 == 3) ? 0 : (s + 1);
    }
#undef ISSUE_STAGE

    // ---- epilogue: fp32 stores (+bias)
#pragma unroll
    for (int mi = 0; mi < 4; mi++) {
        const int row0 = tileM + warp_m * 64 + mi * 16 + g;
#pragma unroll
        for (int nj = 0; nj < 4; nj++) {
            const int col = tileN + warp_n * 32 + nj * 8 + 2 * tig;
            float2 bv = {0.0f, 0.0f};
            if (bias) bv = *(const float2*)(bias + col);
            float2 lo = { acc[mi][nj][0] + bv.x, acc[mi][nj][1] + bv.y };
            float2 hi = { acc[mi][nj][2] + bv.x, acc[mi][nj][3] + bv.y };
            *(float2*)(C + (size_t)row0 * Nld + col)       = lo;
            *(float2*)(C + (size_t)(row0 + 8) * Nld + col) = hi;
        }
    }
}

// ---------------------------------------------------------------------------
// prep kernels: fp16 split2 operand construction
// A' = [xh | xh | xl]   (so that A'@B'^T with B'=[Wh|Wl|Wh] = ah*bh+ah*bl+al*bh)
// ---------------------------------------------------------------------------
__global__ void __launch_bounds__(256)
convert_x(const float* __restrict__ x, __half* __restrict__ Ax)
{
    const int idx = blockIdx.x * blockDim.x + threadIdx.x;   // < MTOT*DIM
    const int m = idx >> 10;
    const int d = idx & (DIM - 1);
    float v = x[idx];
    __half h = __float2half_rn(v);
    __half l = __float2half_rn(v - __half2float(h));
    size_t base = (size_t)m * NQKV;
    Ax[base + d]            = h;
    Ax[base + DIM + d]      = h;
    Ax[base + 2 * DIM + d]  = l;
}

__global__ void __launch_bounds__(256)
convert_w(const float* __restrict__ Wq, const float* __restrict__ Wk,
          const float* __restrict__ Wv, __half* __restrict__ Bw)
{
    const int idx = blockIdx.x * blockDim.x + threadIdx.x;   // < DIM*DIM
    const int n = idx >> 10;
    const int k = idx & (DIM - 1);
    const float* Ws[3] = { Wq, Wk, Wv };
#pragma unroll
    for (int w = 0; w < 3; w++) {
        float v = Ws[w][idx];
        __half h = __float2half_rn(v);
        __half l = __float2half_rn(v - __half2float(h));
        size_t base = (size_t)(w * DIM + n) * NQKV;
        Bw[base + k]            = h;
        Bw[base + DIM + k]      = l;
        Bw[base + 2 * DIM + k]  = h;
    }
}

__global__ void __launch_bounds__(256)
concat_bias(const float* __restrict__ bq, const float* __restrict__ bk,
            const float* __restrict__ bv, float* __restrict__ b3)
{
    const int i = blockIdx.x * blockDim.x + threadIdx.x;     // < NQKV
    if (i < DIM)            b3[i] = bq[i];
    else if (i < 2 * DIM)   b3[i] = bk[i - DIM];
    else                    b3[i] = bv[i - 2 * DIM];
}

// ---------------------------------------------------------------------------
// theta: Qe = [cos(Q*inv_wl + pb) | sin(...)] fp16, Ke likewise.
// Q at QKV[m][0..1023], K at QKV[m][1024..2047].
// ---------------------------------------------------------------------------
__global__ void __launch_bounds__(256)
theta_kernel(const float* __restrict__ QKV, const float* __restrict__ pb,
             __half* __restrict__ Qe, __half* __restrict__ Ke)
{
    const int idx = blockIdx.x * blockDim.x + threadIdx.x;   // < MTOT*DIM
    const int d = idx & (DIM - 1);
    const int m = idx >> 10;
    const float WLC = (float)(6.283185307179586 / (double)DIM);
    float wl  = (float)(d + 1) * WLC;
    float inv = 1.0f / (wl + 1e-8f);
    float p   = pb[d];

    size_t qbase = (size_t)m * NQKV;
    float sq, cq, sk, ck;
    sincosf(fmaf(QKV[qbase + d],       inv, p), &sq, &cq);
    sincosf(fmaf(QKV[qbase + DIM + d], inv, p), &sk, &ck);

    size_t base = (size_t)m * DE;
    Qe[base + d]       = __float2half_rn(cq);
    Qe[base + DIM + d] = __float2half_rn(sq);
    Ke[base + d]       = __float2half_rn(ck);
    Ke[base + DIM + d] = __float2half_rn(sk);
}

// ---------------------------------------------------------------------------
// V transpose per batch -> fp16: Vt[b][n][s] = fp16(QKV[b*4096+s][2048+n])
// ---------------------------------------------------------------------------
__global__ void __launch_bounds__(256)
transpose_v(const float* __restrict__ QKV, __half* __restrict__ Vt)
{
    __shared__ float t[32][33];
    const int b  = blockIdx.z;
    const int s0 = blockIdx.y * 32;
    const int n0 = blockIdx.x * 32;
    const int x = threadIdx.x, y = threadIdx.y;   // 32 x 8
#pragma unroll
    for (int i = 0; i < 32; i += 8)
        t[y + i][x] = QKV[(size_t)(b * SEQ + s0 + y + i) * NQKV + 2 * DIM + n0 + x];
    __syncthreads();
    __half* Vb = Vt + (size_t)b * DIM * SEQ;
#pragma unroll
    for (int i = 0; i < 32; i += 8)
        Vb[(size_t)(n0 + y + i) * SEQ + s0 + x] = __float2half_rn(t[x][y + i]);
}

// ---------------------------------------------------------------------------
// softmax rows (len SEQ), logits /32; writes fp16 weights to P.
// ---------------------------------------------------------------------------
__global__ void __launch_bounds__(256)
softmax_rows(const float* __restrict__ S, __half* __restrict__ P)
{
    __shared__ float sm[8];
    const float* p = S + (size_t)blockIdx.x * SEQ;
    __half* po = P + (size_t)blockIdx.x * SEQ;
    const float4* p4 = (const float4*)p;
    const int t    = threadIdx.x;
    const int lane = t & 31;
    const int wid  = t >> 5;
    const float SCALE = 0.03125f;   // 1/sqrt(1024)

    float v[16];
    float mx = -1e30f;
#pragma unroll
    for (int i = 0; i < 4; i++) {
        float4 x = p4[t + i * 256];
        v[4*i+0] = x.x * SCALE; v[4*i+1] = x.y * SCALE;
        v[4*i+2] = x.z * SCALE; v[4*i+3] = x.w * SCALE;
        mx = fmaxf(mx, fmaxf(fmaxf(v[4*i+0], v[4*i+1]),
                             fmaxf(v[4*i+2], v[4*i+3])));
    }
#pragma unroll
    for (int off = 16; off >= 1; off >>= 1)
        mx = fmaxf(mx, __shfl_xor_sync(0xffffffffu, mx, off));
    if (lane == 0) sm[wid] = mx;
    __syncthreads();
    mx = sm[0];
#pragma unroll
    for (int w = 1; w < 8; w++) mx = fmaxf(mx, sm[w]);
    __syncthreads();

    float sum = 0.0f;
#pragma unroll
    for (int i = 0; i < 16; i++) { v[i] = expf(v[i] - mx); sum += v[i]; }
#pragma unroll
    for (int off = 16; off >= 1; off >>= 1)
        sum += __shfl_xor_sync(0xffffffffu, sum, off);
    if (lane == 0) sm[wid] = sum;
    __syncthreads();
    sum = sm[0];
#pragma unroll
    for (int w = 1; w < 8; w++) sum += sm[w];
    float inv = 1.0f / sum;

    __half2* po2 = (__half2*)po;
#pragma unroll
    for (int i = 0; i < 4; i++) {
        const int e = 4 * (t + i * 256);
        po2[e / 2]     = __floats2half2_rn(v[4*i+0] * inv, v[4*i+1] * inv);
        po2[e / 2 + 1] = __floats2half2_rn(v[4*i+2] * inv, v[4*i+3] * inv);
    }
}

// ---------------------------------------------------------------------------
extern "C" void kernel_launch(void* const* d_in, const int* in_sizes, int n_in,
                              void* d_out, int out_size)
{
    const float* x  = (const float*)d_in[0];
    const float* Wq = (const float*)d_in[1];
    const float* bq = (const float*)d_in[2];
    const float* Wk = (const float*)d_in[3];
    const float* bk = (const float*)d_in[4];
    const float* Wv = (const float*)d_in[5];
    const float* bv = (const float*)d_in[6];
    const float* pb = (const float*)d_in[7];
    float* out = (float*)d_out;

    __half *Ax, *Bw, *Qe, *Ke, *Vt, *P;
    float *b3, *QKV, *Sm;
    cudaGetSymbolAddress((void**)&Ax,  g_Ax);
    cudaGetSymbolAddress((void**)&Bw,  g_Bw);
    cudaGetSymbolAddress((void**)&b3,  g_bias3);
    cudaGetSymbolAddress((void**)&QKV, g_QKV);
    cudaGetSymbolAddress((void**)&Qe,  g_Qe);
    cudaGetSymbolAddress((void**)&Ke,  g_Ke);
    cudaGetSymbolAddress((void**)&Vt,  g_Vt);
    cudaGetSymbolAddress((void**)&Sm,  g_S);
    cudaGetSymbolAddress((void**)&P,   g_P);

    cudaFuncSetAttribute(hgemm_nt,
                         cudaFuncAttributeMaxDynamicSharedMemorySize,
                         H_SMEM_BYTES);

    // 0) build fp16 split2 operands
    convert_x<<<(MTOT * DIM) / 256, 256>>>(x, Ax);
    convert_w<<<(DIM * DIM) / 256, 256>>>(Wq, Wk, Wv, Bw);
    concat_bias<<<NQKV / 256, 256>>>(bq, bk, bv, b3);

    // 1) fused QKV projection: [8192,3072] = Ax @ Bw^T + b3 (fp16 split2)
    dim3 gProj(NQKV / 128, MTOT / 128, 1);
    hgemm_nt<<<gProj, 256, H_SMEM_BYTES>>>(
        Ax, Bw, b3, QKV, NQKV, NQKV, 0, 0, 0);

    // 2) theta -> [cos | sin] fp16
    theta_kernel<<<(MTOT * DIM) / 256, 256>>>(QKV, pb, Qe, Ke);

    // 3) V transpose -> fp16 [DIM][SEQ] per batch
    dim3 gT(DIM / 32, SEQ / 32, BATCH);
    transpose_v<<<gT, dim3(32, 8)>>>(QKV, Vt);

    // 4) sim = Qe @ Ke^T per batch (fp16 mma k16)
    dim3 gSim(SEQ / 128, SEQ / 128, BATCH);
    hgemm_nt<<<gSim, 256, H_SMEM_BYTES>>>(
        Qe, Ke, nullptr, Sm, SEQ, DE,
        (size_t)SEQ * DE, (size_t)SEQ * DE, (size_t)SEQ * SEQ);

    // 5) softmax(sim / 32) rows -> fp16 weights
    softmax_rows<<<BATCH * SEQ, 256>>>(Sm, P);

    // 6) out = P @ Vt^T per batch (fp16 mma k16)
    dim3 gPV(DIM / 128, SEQ / 128, BATCH);
    hgemm_nt<<<gPV, 256, H_SMEM_BYTES>>>(
        P, Vt, nullptr, out, DIM, SEQ,
        (size_t)SEQ * SEQ, (size_t)DIM * SEQ, (size_t)SEQ * DIM);
}

// round 9
// speedup vs baseline: 3.0769x; 1.2666x over previous
#include <cuda_runtime.h>
#include <cuda_fp16.h>
#include <math.h>
#include <stdint.h>

// Problem sizes (fixed)
#define BATCH 2
#define SEQ   4096
#define DIM   1024
#define MTOT  (BATCH * SEQ)     // 8192
#define DE    (2 * DIM)         // 2048  (cos || sin concatenated)
#define NQKV  (3 * DIM)         // 3072

// ---------------- scratch (device globals; no allocation allowed) ----------
__device__ __half g_Ax [(size_t)MTOT * NQKV];          // [8192][3072] = [xh|xh|xl]
__device__ __half g_Bw [(size_t)NQKV * NQKV];          // [3072][3072] rows: [Wh|Wl|Wh]
__device__ float  g_bias3[NQKV];
__device__ float  g_QKV[(size_t)MTOT * NQKV];          // [8192][3072] = [Q|K|V] fp32
__device__ __half g_Qe[(size_t)MTOT * DE];             // [8192][2048] = [cos|sin]
__device__ __half g_Ke[(size_t)MTOT * DE];
__device__ __half g_Vt[(size_t)MTOT * DIM];            // per batch [DIM][SEQ]
__device__ float  g_S [(size_t)BATCH * SEQ * SEQ];     // scores fp32 (134 MB)
__device__ __half g_P [(size_t)BATCH * SEQ * SEQ];     // weights fp16 (67 MB)

// ============================ helpers =======================================
__device__ __forceinline__ uint32_t smem_u32(const void* p) {
    uint32_t a;
    asm("{ .reg .u64 t; cvta.to.shared.u64 t, %1; cvt.u32.u64 %0, t; }"
        : "=r"(a) : "l"(p));
    return a;
}

__device__ __forceinline__ void cpasync16(uint32_t saddr, const void* gaddr) {
    asm volatile("cp.async.cg.shared.global [%0], [%1], 16;"
                 :: "r"(saddr), "l"(gaddr) : "memory");
}

__device__ __forceinline__ void ldsm_x4(uint32_t r[4], uint32_t addr) {
    asm volatile("ldmatrix.sync.aligned.m8n8.x4.shared.b16 {%0,%1,%2,%3}, [%4];"
                 : "=r"(r[0]), "=r"(r[1]), "=r"(r[2]), "=r"(r[3])
                 : "r"(addr));
}

__device__ __forceinline__ void mma_f16(float c[4], const uint32_t a[4],
                                        const uint32_t b[2]) {
    asm volatile(
        "mma.sync.aligned.m16n8k16.row.col.f32.f16.f16.f32 "
        "{%0,%1,%2,%3}, {%4,%5,%6,%7}, {%8,%9}, {%0,%1,%2,%3};"
        : "+f"(c[0]), "+f"(c[1]), "+f"(c[2]), "+f"(c[3])
        : "r"(a[0]), "r"(a[1]), "r"(a[2]), "r"(a[3]),
          "r"(b[0]), "r"(b[1]));
}

// ============================================================================
// fp16 tensor-core NT GEMM via mma.sync.m16n8k16:
//   C[M,N] = A[M,K] @ B[N,K]^T (+bias), fp32 accumulate/output.
// 128x128 CTA tile (k-tile = 64 halfs = 128B/row), 3-stage cp.async ring,
// 256 threads (8 warps, 2x4, warp tile 64x32), rows padded to 144B
// (conflict-free ldmatrix). __launch_bounds__(256,2) caps regs at 128 so
// 2 CTAs co-reside per SM (220 KB smem / 64K regs both fit).
// M%128==0, N%128==0, K%64==0.
// ============================================================================
#define H_STAGE_BYTES  36864              // 2 * 128 rows * 144 B
#define H_SMEM_BYTES   (3 * H_STAGE_BYTES)

__global__ void __launch_bounds__(256, 2)
hgemm_nt(const __half* __restrict__ A, const __half* __restrict__ B,
         const float* __restrict__ bias, float* __restrict__ C,
         int Nld, int K,
         size_t strA, size_t strB, size_t strC)
{
    extern __shared__ float dynsmem[];
    const uint32_t sb = smem_u32(dynsmem);

    const int tid  = threadIdx.x;
    const int wid  = tid >> 5;
    const int lane = tid & 31;

    A += strA * blockIdx.z;
    B += strB * blockIdx.z;
    C += strC * blockIdx.z;
    const int tileM = blockIdx.y * 128;
    const int tileN = blockIdx.x * 128;

    // ---- loader: thread covers rows baseRow + 32*i (i<4), 16B seg of 128B row
    const int baseRow = tid >> 3;      // 0..31
    const int seg     = tid & 7;       // 0..7
    const __half* Ath = A + (size_t)(tileM + baseRow) * K + seg * 8;
    const __half* Bth = B + (size_t)(tileN + baseRow) * K + seg * 8;
    const uint32_t thoff = (uint32_t)(baseRow * 144 + seg * 16);

#define ISSUE_STAGE(KT, S) do {                                               \
    uint32_t _sa = sb + (uint32_t)(S) * H_STAGE_BYTES + thoff;                \
    const __half* _ga = Ath + (size_t)(KT) * 64;                              \
    const __half* _gb = Bth + (size_t)(KT) * 64;                              \
    _Pragma("unroll")                                                         \
    for (int _i = 0; _i < 4; _i++)                                            \
        cpasync16(_sa + _i * (32u * 144u), _ga + (size_t)_i * 32 * K);        \
    _Pragma("unroll")                                                         \
    for (int _i = 0; _i < 4; _i++)                                            \
        cpasync16(_sa + 18432u + _i * (32u * 144u), _gb + (size_t)_i * 32 * K); \
    asm volatile("cp.async.commit_group;" ::: "memory");                      \
} while (0)

    const int nkt = K >> 6;            // 64 halfs per k-tile
    ISSUE_STAGE(0, 0);
    ISSUE_STAGE(1, 1);

    // ---- compute mapping
    const int warp_m = wid >> 2;       // 0..1  -> 64 rows
    const int warp_n = wid & 3;        // 0..3  -> 32 cols
    const int g   = lane >> 2;         // 0..7
    const int tig = lane & 3;          // 0..3

    // ldmatrix lane addresses (bytes):
    const uint32_t laneA = (uint32_t)((lane & 15) * 144 + (lane >> 4) * 16);
    const uint32_t laneB = (uint32_t)(((lane & 7) + ((lane >> 4) & 1) * 8) * 144
                                      + ((lane >> 3) & 1) * 16);

    float acc[4][4][4];
#pragma unroll
    for (int mi = 0; mi < 4; mi++)
#pragma unroll
        for (int nj = 0; nj < 4; nj++)
#pragma unroll
            for (int r = 0; r < 4; r++) acc[mi][nj][r] = 0.0f;

    int s = 0;   // stage of tile kt
    for (int kt = 0; kt < nkt; ++kt) {
        if (kt + 2 < nkt) {
            asm volatile("cp.async.wait_group 1;" ::: "memory");
        } else {
            asm volatile("cp.async.wait_group 0;" ::: "memory");
        }
        __syncthreads();

        if (kt + 2 < nkt) {
            const int s2 = (s + 2 >= 3) ? (s - 1) : (s + 2);
            ISSUE_STAGE(kt + 2, s2);
        }

        const uint32_t stAddr = sb + (uint32_t)s * H_STAGE_BYTES;
        const uint32_t aBase = stAddr + (uint32_t)(warp_m * 64) * 144 + laneA;
        const uint32_t bBase = stAddr + 18432u + (uint32_t)(warp_n * 32) * 144 + laneB;

#pragma unroll
        for (int ks = 0; ks < 4; ++ks) {        // 4 x k16 per 64-half tile
            uint32_t afr[4][4];
            uint32_t bfr[4][2];
            {
                uint32_t t0[4], t1[4];
#pragma unroll
                for (int mi = 0; mi < 4; mi++)
                    ldsm_x4(afr[mi], aBase + mi * 2304u + ks * 32u);
                ldsm_x4(t0, bBase + ks * 32u);            // nj 0,1
                ldsm_x4(t1, bBase + 2304u + ks * 32u);    // nj 2,3
                bfr[0][0] = t0[0]; bfr[0][1] = t0[1];
                bfr[1][0] = t0[2]; bfr[1][1] = t0[3];
                bfr[2][0] = t1[0]; bfr[2][1] = t1[1];
                bfr[3][0] = t1[2]; bfr[3][1] = t1[3];
            }
#pragma unroll
            for (int mi = 0; mi < 4; mi++)
#pragma unroll
                for (int nj = 0; nj < 4; nj++)
                    mma_f16(acc[mi][nj], afr[mi], bfr[nj]);
        }
        __syncthreads();
        s = (s + 1 == 3) ? 0 : (s + 1);
    }
#undef ISSUE_STAGE

    // ---- epilogue: fp32 stores (+bias)
#pragma unroll
    for (int mi = 0; mi < 4; mi++) {
        const int row0 = tileM + warp_m * 64 + mi * 16 + g;
#pragma unroll
        for (int nj = 0; nj < 4; nj++) {
            const int col = tileN + warp_n * 32 + nj * 8 + 2 * tig;
            float2 bv = {0.0f, 0.0f};
            if (bias) bv = *(const float2*)(bias + col);
            float2 lo = { acc[mi][nj][0] + bv.x, acc[mi][nj][1] + bv.y };
            float2 hi = { acc[mi][nj][2] + bv.x, acc[mi][nj][3] + bv.y };
            *(float2*)(C + (size_t)row0 * Nld + col)       = lo;
            *(float2*)(C + (size_t)(row0 + 8) * Nld + col) = hi;
        }
    }
}

// ---------------------------------------------------------------------------
// prep kernels: fp16 split2 operand construction
// A' = [xh | xh | xl]   (so that A'@B'^T with B'=[Wh|Wl|Wh] = ah*bh+ah*bl+al*bh)
// ---------------------------------------------------------------------------
__global__ void __launch_bounds__(256)
convert_x(const float* __restrict__ x, __half* __restrict__ Ax)
{
    const int idx = blockIdx.x * blockDim.x + threadIdx.x;   // < MTOT*DIM
    const int m = idx >> 10;
    const int d = idx & (DIM - 1);
    float v = x[idx];
    __half h = __float2half_rn(v);
    __half l = __float2half_rn(v - __half2float(h));
    size_t base = (size_t)m * NQKV;
    Ax[base + d]            = h;
    Ax[base + DIM + d]      = h;
    Ax[base + 2 * DIM + d]  = l;
}

__global__ void __launch_bounds__(256)
convert_w(const float* __restrict__ Wq, const float* __restrict__ Wk,
          const float* __restrict__ Wv, __half* __restrict__ Bw)
{
    const int idx = blockIdx.x * blockDim.x + threadIdx.x;   // < DIM*DIM
    const int n = idx >> 10;
    const int k = idx & (DIM - 1);
    const float* Ws[3] = { Wq, Wk, Wv };
#pragma unroll
    for (int w = 0; w < 3; w++) {
        float v = Ws[w][idx];
        __half h = __float2half_rn(v);
        __half l = __float2half_rn(v - __half2float(h));
        size_t base = (size_t)(w * DIM + n) * NQKV;
        Bw[base + k]            = h;
        Bw[base + DIM + k]      = l;
        Bw[base + 2 * DIM + k]  = h;
    }
}

__global__ void __launch_bounds__(256)
concat_bias(const float* __restrict__ bq, const float* __restrict__ bk,
            const float* __restrict__ bv, float* __restrict__ b3)
{
    const int i = blockIdx.x * blockDim.x + threadIdx.x;     // < NQKV
    if (i < DIM)            b3[i] = bq[i];
    else if (i < 2 * DIM)   b3[i] = bk[i - DIM];
    else                    b3[i] = bv[i - 2 * DIM];
}

// ---------------------------------------------------------------------------
// theta: Qe = [cos(Q*inv_wl + pb) | sin(...)] fp16, Ke likewise.
// ---------------------------------------------------------------------------
__global__ void __launch_bounds__(256)
theta_kernel(const float* __restrict__ QKV, const float* __restrict__ pb,
             __half* __restrict__ Qe, __half* __restrict__ Ke)
{
    const int idx = blockIdx.x * blockDim.x + threadIdx.x;   // < MTOT*DIM
    const int d = idx & (DIM - 1);
    const int m = idx >> 10;
    const float WLC = (float)(6.283185307179586 / (double)DIM);
    float wl  = (float)(d + 1) * WLC;
    float inv = 1.0f / (wl + 1e-8f);
    float p   = pb[d];

    size_t qbase = (size_t)m * NQKV;
    float sq, cq, sk, ck;
    sincosf(fmaf(QKV[qbase + d],       inv, p), &sq, &cq);
    sincosf(fmaf(QKV[qbase + DIM + d], inv, p), &sk, &ck);

    size_t base = (size_t)m * DE;
    Qe[base + d]       = __float2half_rn(cq);
    Qe[base + DIM + d] = __float2half_rn(sq);
    Ke[base + d]       = __float2half_rn(ck);
    Ke[base + DIM + d] = __float2half_rn(sk);
}

// ---------------------------------------------------------------------------
// V transpose per batch -> fp16: Vt[b][n][s] = fp16(QKV[b*4096+s][2048+n])
// ---------------------------------------------------------------------------
__global__ void __launch_bounds__(256)
transpose_v(const float* __restrict__ QKV, __half* __restrict__ Vt)
{
    __shared__ float t[32][33];
    const int b  = blockIdx.z;
    const int s0 = blockIdx.y * 32;
    const int n0 = blockIdx.x * 32;
    const int x = threadIdx.x, y = threadIdx.y;   // 32 x 8
#pragma unroll
    for (int i = 0; i < 32; i += 8)
        t[y + i][x] = QKV[(size_t)(b * SEQ + s0 + y + i) * NQKV + 2 * DIM + n0 + x];
    __syncthreads();
    __half* Vb = Vt + (size_t)b * DIM * SEQ;
#pragma unroll
    for (int i = 0; i < 32; i += 8)
        Vb[(size_t)(n0 + y + i) * SEQ + s0 + x] = __float2half_rn(t[x][y + i]);
}

// ---------------------------------------------------------------------------
// softmax rows (len SEQ), logits /32; writes fp16 weights to P.
// ---------------------------------------------------------------------------
__global__ void __launch_bounds__(256)
softmax_rows(const float* __restrict__ S, __half* __restrict__ P)
{
    __shared__ float sm[8];
    const float* p = S + (size_t)blockIdx.x * SEQ;
    __half* po = P + (size_t)blockIdx.x * SEQ;
    const float4* p4 = (const float4*)p;
    const int t    = threadIdx.x;
    const int lane = t & 31;
    const int wid  = t >> 5;
    const float SCALE = 0.03125f;   // 1/sqrt(1024)

    float v[16];
    float mx = -1e30f;
#pragma unroll
    for (int i = 0; i < 4; i++) {
        float4 x = p4[t + i * 256];
        v[4*i+0] = x.x * SCALE; v[4*i+1] = x.y * SCALE;
        v[4*i+2] = x.z * SCALE; v[4*i+3] = x.w * SCALE;
        mx = fmaxf(mx, fmaxf(fmaxf(v[4*i+0], v[4*i+1]),
                             fmaxf(v[4*i+2], v[4*i+3])));
    }
#pragma unroll
    for (int off = 16; off >= 1; off >>= 1)
        mx = fmaxf(mx, __shfl_xor_sync(0xffffffffu, mx, off));
    if (lane == 0) sm[wid] = mx;
    __syncthreads();
    mx = sm[0];
#pragma unroll
    for (int w = 1; w < 8; w++) mx = fmaxf(mx, sm[w]);
    __syncthreads();

    float sum = 0.0f;
#pragma unroll
    for (int i = 0; i < 16; i++) { v[i] = expf(v[i] - mx); sum += v[i]; }
#pragma unroll
    for (int off = 16; off >= 1; off >>= 1)
        sum += __shfl_xor_sync(0xffffffffu, sum, off);
    if (lane == 0) sm[wid] = sum;
    __syncthreads();
    sum = sm[0];
#pragma unroll
    for (int w = 1; w < 8; w++) sum += sm[w];
    float inv = 1.0f / sum;

    __half2* po2 = (__half2*)po;
#pragma unroll
    for (int i = 0; i < 4; i++) {
        const int e = 4 * (t + i * 256);
        po2[e / 2]     = __floats2half2_rn(v[4*i+0] * inv, v[4*i+1] * inv);
        po2[e / 2 + 1] = __floats2half2_rn(v[4*i+2] * inv, v[4*i+3] * inv);
    }
}

// ---------------------------------------------------------------------------
extern "C" void kernel_launch(void* const* d_in, const int* in_sizes, int n_in,
                              void* d_out, int out_size)
{
    const float* x  = (const float*)d_in[0];
    const float* Wq = (const float*)d_in[1];
    const float* bq = (const float*)d_in[2];
    const float* Wk = (const float*)d_in[3];
    const float* bk = (const float*)d_in[4];
    const float* Wv = (const float*)d_in[5];
    const float* bv = (const float*)d_in[6];
    const float* pb = (const float*)d_in[7];
    float* out = (float*)d_out;

    __half *Ax, *Bw, *Qe, *Ke, *Vt, *P;
    float *b3, *QKV, *Sm;
    cudaGetSymbolAddress((void**)&Ax,  g_Ax);
    cudaGetSymbolAddress((void**)&Bw,  g_Bw);
    cudaGetSymbolAddress((void**)&b3,  g_bias3);
    cudaGetSymbolAddress((void**)&QKV, g_QKV);
    cudaGetSymbolAddress((void**)&Qe,  g_Qe);
    cudaGetSymbolAddress((void**)&Ke,  g_Ke);
    cudaGetSymbolAddress((void**)&Vt,  g_Vt);
    cudaGetSymbolAddress((void**)&Sm,  g_S);
    cudaGetSymbolAddress((void**)&P,   g_P);

    cudaFuncSetAttribute(hgemm_nt,
                         cudaFuncAttributeMaxDynamicSharedMemorySize,
                         H_SMEM_BYTES);

    // 0) build fp16 split2 operands
    convert_x<<<(MTOT * DIM) / 256, 256>>>(x, Ax);
    convert_w<<<(DIM * DIM) / 256, 256>>>(Wq, Wk, Wv, Bw);
    concat_bias<<<NQKV / 256, 256>>>(bq, bk, bv, b3);

    // 1) fused QKV projection: [8192,3072] = Ax @ Bw^T + b3 (fp16 split2)
    dim3 gProj(NQKV / 128, MTOT / 128, 1);
    hgemm_nt<<<gProj, 256, H_SMEM_BYTES>>>(
        Ax, Bw, b3, QKV, NQKV, NQKV, 0, 0, 0);

    // 2) theta -> [cos | sin] fp16
    theta_kernel<<<(MTOT * DIM) / 256, 256>>>(QKV, pb, Qe, Ke);

    // 3) V transpose -> fp16 [DIM][SEQ] per batch
    dim3 gT(DIM / 32, SEQ / 32, BATCH);
    transpose_v<<<gT, dim3(32, 8)>>>(QKV, Vt);

    // 4) sim = Qe @ Ke^T per batch (fp16 mma k16)
    dim3 gSim(SEQ / 128, SEQ / 128, BATCH);
    hgemm_nt<<<gSim, 256, H_SMEM_BYTES>>>(
        Qe, Ke, nullptr, Sm, SEQ, DE,
        (size_t)SEQ * DE, (size_t)SEQ * DE, (size_t)SEQ * SEQ);

    // 5) softmax(sim / 32) rows -> fp16 weights
    softmax_rows<<<BATCH * SEQ, 256>>>(Sm, P);

    // 6) out = P @ Vt^T per batch (fp16 mma k16)
    dim3 gPV(DIM / 128, SEQ / 128, BATCH);
    hgemm_nt<<<gPV, 256, H_SMEM_BYTES>>>(
        P, Vt, nullptr, out, DIM, SEQ,
        (size_t)SEQ * SEQ, (size_t)DIM * SEQ, (size_t)SEQ * DIM);
}

// round 10
// speedup vs baseline: 3.1176x; 1.0132x over previous
#include <cuda_runtime.h>
#include <cuda_fp16.h>
#include <math.h>
#include <stdint.h>

// Problem sizes (fixed)
#define BATCH 2
#define SEQ   4096
#define DIM   1024
#define MTOT  (BATCH * SEQ)     // 8192
#define DE    (2 * DIM)         // 2048  (cos || sin concatenated)
#define NQKV  (3 * DIM)         // 3072

// ---------------- scratch (device globals; no allocation allowed) ----------
__device__ __half g_Ax [(size_t)MTOT * NQKV];          // [8192][3072] = [xh|xh|xl]
__device__ __half g_Bw [(size_t)NQKV * NQKV];          // [3072][3072] rows: [Wh|Wl|Wh]
__device__ float  g_bias3[NQKV];
__device__ float  g_QKV[(size_t)MTOT * NQKV];          // [8192][3072] = [Q|K|V] fp32
__device__ __half g_Qe[(size_t)MTOT * DE];             // [8192][2048] = [cos|sin]
__device__ __half g_Ke[(size_t)MTOT * DE];
__device__ __half g_Vt[(size_t)MTOT * DIM];            // per batch [DIM][SEQ]
__device__ float  g_S [(size_t)BATCH * SEQ * SEQ];     // scores fp32 (134 MB)
__device__ __half g_P [(size_t)BATCH * SEQ * SEQ];     // weights fp16 (67 MB)

// ============================ helpers =======================================
__device__ __forceinline__ uint32_t smem_u32(const void* p) {
    uint32_t a;
    asm("{ .reg .u64 t; cvta.to.shared.u64 t, %1; cvt.u32.u64 %0, t; }"
        : "=r"(a) : "l"(p));
    return a;
}

__device__ __forceinline__ void cpasync16(uint32_t saddr, const void* gaddr) {
    asm volatile("cp.async.cg.shared.global [%0], [%1], 16;"
                 :: "r"(saddr), "l"(gaddr) : "memory");
}

__device__ __forceinline__ void ldsm_x4(uint32_t r[4], uint32_t addr) {
    asm volatile("ldmatrix.sync.aligned.m8n8.x4.shared.b16 {%0,%1,%2,%3}, [%4];"
                 : "=r"(r[0]), "=r"(r[1]), "=r"(r[2]), "=r"(r[3])
                 : "r"(addr));
}

__device__ __forceinline__ void mma_f16(float c[4], const uint32_t a[4],
                                        const uint32_t b[2]) {
    asm volatile(
        "mma.sync.aligned.m16n8k16.row.col.f32.f16.f16.f32 "
        "{%0,%1,%2,%3}, {%4,%5,%6,%7}, {%8,%9}, {%0,%1,%2,%3};"
        : "+f"(c[0]), "+f"(c[1]), "+f"(c[2]), "+f"(c[3])
        : "r"(a[0]), "r"(a[1]), "r"(a[2]), "r"(a[3]),
          "r"(b[0]), "r"(b[1]));
}

// ============================================================================
// fp16 tensor-core NT GEMM via mma.sync.m16n8k16:
//   C[M,N] = A[M,K] @ B[N,K]^T (+bias), fp32 accumulate/output.
// 128x128 CTA tile (k-tile = 64 halfs), 3-stage cp.async ring, 256 threads
// (8 warps, 2x4, warp tile 64x32), 144B-padded rows (conflict-free ldmatrix).
// __launch_bounds__(256,2): 2 CTAs/SM. ONE barrier per k-tile (top barrier
// doubles as the stage-overwrite guard). Fragments double-buffered across
// k16 steps so ldmatrix for ks+1 overlaps MMAs of ks.
// M%128==0, N%128==0, K%64==0.
// ============================================================================
#define H_STAGE_BYTES  36864              // 2 * 128 rows * 144 B
#define H_SMEM_BYTES   (3 * H_STAGE_BYTES)

__global__ void __launch_bounds__(256, 2)
hgemm_nt(const __half* __restrict__ A, const __half* __restrict__ B,
         const float* __restrict__ bias, float* __restrict__ C,
         int Nld, int K,
         size_t strA, size_t strB, size_t strC)
{
    extern __shared__ float dynsmem[];
    const uint32_t sb = smem_u32(dynsmem);

    const int tid  = threadIdx.x;
    const int wid  = tid >> 5;
    const int lane = tid & 31;

    A += strA * blockIdx.z;
    B += strB * blockIdx.z;
    C += strC * blockIdx.z;
    const int tileM = blockIdx.y * 128;
    const int tileN = blockIdx.x * 128;

    // ---- loader: thread covers rows baseRow + 32*i (i<4), 16B seg of 128B row
    const int baseRow = tid >> 3;      // 0..31
    const int seg     = tid & 7;       // 0..7
    const __half* Ath = A + (size_t)(tileM + baseRow) * K + seg * 8;
    const __half* Bth = B + (size_t)(tileN + baseRow) * K + seg * 8;
    const uint32_t thoff = (uint32_t)(baseRow * 144 + seg * 16);

#define ISSUE_STAGE(KT, S) do {                                               \
    uint32_t _sa = sb + (uint32_t)(S) * H_STAGE_BYTES + thoff;                \
    const __half* _ga = Ath + (size_t)(KT) * 64;                              \
    const __half* _gb = Bth + (size_t)(KT) * 64;                              \
    _Pragma("unroll")                                                         \
    for (int _i = 0; _i < 4; _i++)                                            \
        cpasync16(_sa + _i * (32u * 144u), _ga + (size_t)_i * 32 * K);        \
    _Pragma("unroll")                                                         \
    for (int _i = 0; _i < 4; _i++)                                            \
        cpasync16(_sa + 18432u + _i * (32u * 144u), _gb + (size_t)_i * 32 * K); \
    asm volatile("cp.async.commit_group;" ::: "memory");                      \
} while (0)

    const int nkt = K >> 6;            // 64 halfs per k-tile
    ISSUE_STAGE(0, 0);
    ISSUE_STAGE(1, 1);

    // ---- compute mapping
    const int warp_m = wid >> 2;       // 0..1  -> 64 rows
    const int warp_n = wid & 3;        // 0..3  -> 32 cols
    const int g   = lane >> 2;         // 0..7
    const int tig = lane & 3;          // 0..3

    // ldmatrix lane addresses (bytes):
    const uint32_t laneA = (uint32_t)((lane & 15) * 144 + (lane >> 4) * 16);
    const uint32_t laneB = (uint32_t)(((lane & 7) + ((lane >> 4) & 1) * 8) * 144
                                      + ((lane >> 3) & 1) * 16);

// load fragments for step KS into buffer slot BUF
#define LOAD_FRAGS(BUF, KS) do {                                              \
    uint32_t t0[4], t1[4];                                                    \
    _Pragma("unroll")                                                         \
    for (int _mi = 0; _mi < 4; _mi++)                                         \
        ldsm_x4(afr[BUF][_mi], aBase + _mi * 2304u + (KS) * 32u);             \
    ldsm_x4(t0, bBase + (KS) * 32u);                                          \
    ldsm_x4(t1, bBase + 2304u + (KS) * 32u);                                  \
    bfr[BUF][0][0] = t0[0]; bfr[BUF][0][1] = t0[1];                           \
    bfr[BUF][1][0] = t0[2]; bfr[BUF][1][1] = t0[3];                           \
    bfr[BUF][2][0] = t1[0]; bfr[BUF][2][1] = t1[1];                           \
    bfr[BUF][3][0] = t1[2]; bfr[BUF][3][1] = t1[3];                           \
} while (0)

    float acc[4][4][4];
#pragma unroll
    for (int mi = 0; mi < 4; mi++)
#pragma unroll
        for (int nj = 0; nj < 4; nj++)
#pragma unroll
            for (int r = 0; r < 4; r++) acc[mi][nj][r] = 0.0f;

    int s = 0;   // stage of tile kt
    for (int kt = 0; kt < nkt; ++kt) {
        if (kt + 2 < nkt) {
            asm volatile("cp.async.wait_group 1;" ::: "memory");
        } else {
            asm volatile("cp.async.wait_group 0;" ::: "memory");
        }
        // Single barrier: makes tile kt visible AND proves every warp has
        // finished computing tile kt-1 (whose stage is overwritten below).
        __syncthreads();

        if (kt + 2 < nkt) {
            const int s2 = (s + 2 >= 3) ? (s - 1) : (s + 2);
            ISSUE_STAGE(kt + 2, s2);
        }

        const uint32_t stAddr = sb + (uint32_t)s * H_STAGE_BYTES;
        const uint32_t aBase = stAddr + (uint32_t)(warp_m * 64) * 144 + laneA;
        const uint32_t bBase = stAddr + 18432u + (uint32_t)(warp_n * 32) * 144 + laneB;

        uint32_t afr[2][4][4];
        uint32_t bfr[2][4][2];
        LOAD_FRAGS(0, 0);

#pragma unroll
        for (int ks = 0; ks < 4; ++ks) {        // 4 x k16 per 64-half tile
            const int cur = ks & 1;
            if (ks < 3) LOAD_FRAGS(cur ^ 1, ks + 1);
#pragma unroll
            for (int mi = 0; mi < 4; mi++)
#pragma unroll
                for (int nj = 0; nj < 4; nj++)
                    mma_f16(acc[mi][nj], afr[cur][mi], bfr[cur][nj]);
        }
        s = (s + 1 == 3) ? 0 : (s + 1);
    }
#undef ISSUE_STAGE
#undef LOAD_FRAGS

    // ---- epilogue: fp32 stores (+bias)
#pragma unroll
    for (int mi = 0; mi < 4; mi++) {
        const int row0 = tileM + warp_m * 64 + mi * 16 + g;
#pragma unroll
        for (int nj = 0; nj < 4; nj++) {
            const int col = tileN + warp_n * 32 + nj * 8 + 2 * tig;
            float2 bv = {0.0f, 0.0f};
            if (bias) bv = *(const float2*)(bias + col);
            float2 lo = { acc[mi][nj][0] + bv.x, acc[mi][nj][1] + bv.y };
            float2 hi = { acc[mi][nj][2] + bv.x, acc[mi][nj][3] + bv.y };
            *(float2*)(C + (size_t)row0 * Nld + col)       = lo;
            *(float2*)(C + (size_t)(row0 + 8) * Nld + col) = hi;
        }
    }
}

// ---------------------------------------------------------------------------
// prep kernels: fp16 split2 operand construction
// A' = [xh | xh | xl]   (so that A'@B'^T with B'=[Wh|Wl|Wh] = ah*bh+ah*bl+al*bh)
// ---------------------------------------------------------------------------
__global__ void __launch_bounds__(256)
convert_x(const float* __restrict__ x, __half* __restrict__ Ax)
{
    const int idx = blockIdx.x * blockDim.x + threadIdx.x;   // < MTOT*DIM
    const int m = idx >> 10;
    const int d = idx & (DIM - 1);
    float v = x[idx];
    __half h = __float2half_rn(v);
    __half l = __float2half_rn(v - __half2float(h));
    size_t base = (size_t)m * NQKV;
    Ax[base + d]            = h;
    Ax[base + DIM + d]      = h;
    Ax[base + 2 * DIM + d]  = l;
}

__global__ void __launch_bounds__(256)
convert_w(const float* __restrict__ Wq, const float* __restrict__ Wk,
          const float* __restrict__ Wv, __half* __restrict__ Bw)
{
    const int idx = blockIdx.x * blockDim.x + threadIdx.x;   // < DIM*DIM
    const int n = idx >> 10;
    const int k = idx & (DIM - 1);
    const float* Ws[3] = { Wq, Wk, Wv };
#pragma unroll
    for (int w = 0; w < 3; w++) {
        float v = Ws[w][idx];
        __half h = __float2half_rn(v);
        __half l = __float2half_rn(v - __half2float(h));
        size_t base = (size_t)(w * DIM + n) * NQKV;
        Bw[base + k]            = h;
        Bw[base + DIM + k]      = l;
        Bw[base + 2 * DIM + k]  = h;
    }
}

__global__ void __launch_bounds__(256)
concat_bias(const float* __restrict__ bq, const float* __restrict__ bk,
            const float* __restrict__ bv, float* __restrict__ b3)
{
    const int i = blockIdx.x * blockDim.x + threadIdx.x;     // < NQKV
    if (i < DIM)            b3[i] = bq[i];
    else if (i < 2 * DIM)   b3[i] = bk[i - DIM];
    else                    b3[i] = bv[i - 2 * DIM];
}

// ---------------------------------------------------------------------------
// theta: Qe = [cos(Q*inv_wl + pb) | sin(...)] fp16, Ke likewise.
// ---------------------------------------------------------------------------
__global__ void __launch_bounds__(256)
theta_kernel(const float* __restrict__ QKV, const float* __restrict__ pb,
             __half* __restrict__ Qe, __half* __restrict__ Ke)
{
    const int idx = blockIdx.x * blockDim.x + threadIdx.x;   // < MTOT*DIM
    const int d = idx & (DIM - 1);
    const int m = idx >> 10;
    const float WLC = (float)(6.283185307179586 / (double)DIM);
    float wl  = (float)(d + 1) * WLC;
    float inv = 1.0f / (wl + 1e-8f);
    float p   = pb[d];

    size_t qbase = (size_t)m * NQKV;
    float sq, cq, sk, ck;
    sincosf(fmaf(QKV[qbase + d],       inv, p), &sq, &cq);
    sincosf(fmaf(QKV[qbase + DIM + d], inv, p), &sk, &ck);

    size_t base = (size_t)m * DE;
    Qe[base + d]       = __float2half_rn(cq);
    Qe[base + DIM + d] = __float2half_rn(sq);
    Ke[base + d]       = __float2half_rn(ck);
    Ke[base + DIM + d] = __float2half_rn(sk);
}

// ---------------------------------------------------------------------------
// V transpose per batch -> fp16: Vt[b][n][s] = fp16(QKV[b*4096+s][2048+n])
// ---------------------------------------------------------------------------
__global__ void __launch_bounds__(256)
transpose_v(const float* __restrict__ QKV, __half* __restrict__ Vt)
{
    __shared__ float t[32][33];
    const int b  = blockIdx.z;
    const int s0 = blockIdx.y * 32;
    const int n0 = blockIdx.x * 32;
    const int x = threadIdx.x, y = threadIdx.y;   // 32 x 8
#pragma unroll
    for (int i = 0; i < 32; i += 8)
        t[y + i][x] = QKV[(size_t)(b * SEQ + s0 + y + i) * NQKV + 2 * DIM + n0 + x];
    __syncthreads();
    __half* Vb = Vt + (size_t)b * DIM * SEQ;
#pragma unroll
    for (int i = 0; i < 32; i += 8)
        Vb[(size_t)(n0 + y + i) * SEQ + s0 + x] = __float2half_rn(t[x][y + i]);
}

// ---------------------------------------------------------------------------
// softmax rows (len SEQ), logits /32; writes fp16 weights to P.
// ---------------------------------------------------------------------------
__global__ void __launch_bounds__(256)
softmax_rows(const float* __restrict__ S, __half* __restrict__ P)
{
    __shared__ float sm[8];
    const float* p = S + (size_t)blockIdx.x * SEQ;
    __half* po = P + (size_t)blockIdx.x * SEQ;
    const float4* p4 = (const float4*)p;
    const int t    = threadIdx.x;
    const int lane = t & 31;
    const int wid  = t >> 5;
    const float SCALE = 0.03125f;   // 1/sqrt(1024)

    float v[16];
    float mx = -1e30f;
#pragma unroll
    for (int i = 0; i < 4; i++) {
        float4 x = p4[t + i * 256];
        v[4*i+0] = x.x * SCALE; v[4*i+1] = x.y * SCALE;
        v[4*i+2] = x.z * SCALE; v[4*i+3] = x.w * SCALE;
        mx = fmaxf(mx, fmaxf(fmaxf(v[4*i+0], v[4*i+1]),
                             fmaxf(v[4*i+2], v[4*i+3])));
    }
#pragma unroll
    for (int off = 16; off >= 1; off >>= 1)
        mx = fmaxf(mx, __shfl_xor_sync(0xffffffffu, mx, off));
    if (lane == 0) sm[wid] = mx;
    __syncthreads();
    mx = sm[0];
#pragma unroll
    for (int w = 1; w < 8; w++) mx = fmaxf(mx, sm[w]);
    __syncthreads();

    float sum = 0.0f;
#pragma unroll
    for (int i = 0; i < 16; i++) { v[i] = expf(v[i] - mx); sum += v[i]; }
#pragma unroll
    for (int off = 16; off >= 1; off >>= 1)
        sum += __shfl_xor_sync(0xffffffffu, sum, off);
    if (lane == 0) sm[wid] = sum;
    __syncthreads();
    sum = sm[0];
#pragma unroll
    for (int w = 1; w < 8; w++) sum += sm[w];
    float inv = 1.0f / sum;

    __half2* po2 = (__half2*)po;
#pragma unroll
    for (int i = 0; i < 4; i++) {
        const int e = 4 * (t + i * 256);
        po2[e / 2]     = __floats2half2_rn(v[4*i+0] * inv, v[4*i+1] * inv);
        po2[e / 2 + 1] = __floats2half2_rn(v[4*i+2] * inv, v[4*i+3] * inv);
    }
}

// ---------------------------------------------------------------------------
extern "C" void kernel_launch(void* const* d_in, const int* in_sizes, int n_in,
                              void* d_out, int out_size)
{
    const float* x  = (const float*)d_in[0];
    const float* Wq = (const float*)d_in[1];
    const float* bq = (const float*)d_in[2];
    const float* Wk = (const float*)d_in[3];
    const float* bk = (const float*)d_in[4];
    const float* Wv = (const float*)d_in[5];
    const float* bv = (const float*)d_in[6];
    const float* pb = (const float*)d_in[7];
    float* out = (float*)d_out;

    __half *Ax, *Bw, *Qe, *Ke, *Vt, *P;
    float *b3, *QKV, *Sm;
    cudaGetSymbolAddress((void**)&Ax,  g_Ax);
    cudaGetSymbolAddress((void**)&Bw,  g_Bw);
    cudaGetSymbolAddress((void**)&b3,  g_bias3);
    cudaGetSymbolAddress((void**)&QKV, g_QKV);
    cudaGetSymbolAddress((void**)&Qe,  g_Qe);
    cudaGetSymbolAddress((void**)&Ke,  g_Ke);
    cudaGetSymbolAddress((void**)&Vt,  g_Vt);
    cudaGetSymbolAddress((void**)&Sm,  g_S);
    cudaGetSymbolAddress((void**)&P,   g_P);

    cudaFuncSetAttribute(hgemm_nt,
                         cudaFuncAttributeMaxDynamicSharedMemorySize,
                         H_SMEM_BYTES);

    // 0) build fp16 split2 operands
    convert_x<<<(MTOT * DIM) / 256, 256>>>(x, Ax);
    convert_w<<<(DIM * DIM) / 256, 256>>>(Wq, Wk, Wv, Bw);
    concat_bias<<<NQKV / 256, 256>>>(bq, bk, bv, b3);

    // 1) fused QKV projection: [8192,3072] = Ax @ Bw^T + b3 (fp16 split2)
    dim3 gProj(NQKV / 128, MTOT / 128, 1);
    hgemm_nt<<<gProj, 256, H_SMEM_BYTES>>>(
        Ax, Bw, b3, QKV, NQKV, NQKV, 0, 0, 0);

    // 2) theta -> [cos | sin] fp16
    theta_kernel<<<(MTOT * DIM) / 256, 256>>>(QKV, pb, Qe, Ke);

    // 3) V transpose -> fp16 [DIM][SEQ] per batch
    dim3 gT(DIM / 32, SEQ / 32, BATCH);
    transpose_v<<<gT, dim3(32, 8)>>>(QKV, Vt);

    // 4) sim = Qe @ Ke^T per batch (fp16 mma k16)
    dim3 gSim(SEQ / 128, SEQ / 128, BATCH);
    hgemm_nt<<<gSim, 256, H_SMEM_BYTES>>>(
        Qe, Ke, nullptr, Sm, SEQ, DE,
        (size_t)SEQ * DE, (size_t)SEQ * DE, (size_t)SEQ * SEQ);

    // 5) softmax(sim / 32) rows -> fp16 weights
    softmax_rows<<<BATCH * SEQ, 256>>>(Sm, P);

    // 6) out = P @ Vt^T per batch (fp16 mma k16)
    dim3 gPV(DIM / 128, SEQ / 128, BATCH);
    hgemm_nt<<<gPV, 256, H_SMEM_BYTES>>>(
        P, Vt, nullptr, out, DIM, SEQ,
        (size_t)SEQ * SEQ, (size_t)DIM * SEQ, (size_t)SEQ * DIM);
}

// round 11
// speedup vs baseline: 3.4468x; 1.1056x over previous
#include <cuda_runtime.h>
#include <cuda_fp16.h>
#include <math.h>
#include <stdint.h>

// Problem sizes (fixed)
#define BATCH 2
#define SEQ   4096
#define DIM   1024
#define MTOT  (BATCH * SEQ)     // 8192
#define DE    (2 * DIM)         // 2048  (cos || sin concatenated)
#define KQK   (3 * DIM)         // 3072  (split2 K for QK projection)

// ---------------- scratch (device globals; no allocation allowed) ----------
__device__ __half g_Ax [(size_t)MTOT * KQK];           // [8192][3072] = [xh|xh|xl]
__device__ __half g_Bqk[(size_t)DE * KQK];             // [2048][3072]: Wq/Wk rows [Wh|Wl|Wh]
__device__ __half g_Bv [(size_t)DIM * DIM];            // [1024][1024]: Wv fp16
__device__ float  g_bqk[DE];                           // bq | bk
__device__ float  g_V  [(size_t)MTOT * DIM];           // V fp32
__device__ __half g_Qe [(size_t)MTOT * DE];            // [8192][2048] = [cos|sin]
__device__ __half g_Ke [(size_t)MTOT * DE];
__device__ __half g_Vt [(size_t)MTOT * DIM];           // per batch [DIM][SEQ]
__device__ float  g_S  [(size_t)BATCH * SEQ * SEQ];    // scores fp32 (134 MB)
__device__ __half g_P  [(size_t)BATCH * SEQ * SEQ];    // weights fp16 (67 MB)

// ============================ helpers =======================================
__device__ __forceinline__ uint32_t smem_u32(const void* p) {
    uint32_t a;
    asm("{ .reg .u64 t; cvta.to.shared.u64 t, %1; cvt.u32.u64 %0, t; }"
        : "=r"(a) : "l"(p));
    return a;
}

__device__ __forceinline__ void cpasync16(uint32_t saddr, const void* gaddr) {
    asm volatile("cp.async.cg.shared.global [%0], [%1], 16;"
                 :: "r"(saddr), "l"(gaddr) : "memory");
}

__device__ __forceinline__ void ldsm_x4(uint32_t r[4], uint32_t addr) {
    asm volatile("ldmatrix.sync.aligned.m8n8.x4.shared.b16 {%0,%1,%2,%3}, [%4];"
                 : "=r"(r[0]), "=r"(r[1]), "=r"(r[2]), "=r"(r[3])
                 : "r"(addr));
}

__device__ __forceinline__ void mma_f16(float c[4], const uint32_t a[4],
                                        const uint32_t b[2]) {
    asm volatile(
        "mma.sync.aligned.m16n8k16.row.col.f32.f16.f16.f32 "
        "{%0,%1,%2,%3}, {%4,%5,%6,%7}, {%8,%9}, {%0,%1,%2,%3};"
        : "+f"(c[0]), "+f"(c[1]), "+f"(c[2]), "+f"(c[3])
        : "r"(a[0]), "r"(a[1]), "r"(a[2]), "r"(a[3]),
          "r"(b[0]), "r"(b[1]));
}

#define EPI_STORE 0   // fp32 C (+bias)
#define EPI_THETA 1   // QK projection: sincos(Q*inv_wl + pb) -> Qe/Ke fp16

// ============================================================================
// fp16 tensor-core NT GEMM via mma.sync.m16n8k16:
//   acc[M,N] = A[M,K] @ B[N,K]^T, fp32 accumulate.
// 128x128 CTA tile (k-tile = 64 halfs), 3-stage cp.async ring, 256 threads
// (8 warps, 2x4, warp tile 64x32), 144B-padded rows (conflict-free ldmatrix),
// fragment double-buffering, one barrier per k-tile, 2 CTAs/SM.
// EPI_STORE: C fp32 (+bias).  EPI_THETA: fused Euler phase epilogue.
// M%128==0, N%128==0, K%64==0.
// ============================================================================
#define H_STAGE_BYTES  36864              // 2 * 128 rows * 144 B
#define H_SMEM_BYTES   (3 * H_STAGE_BYTES)

template<int EPI>
__global__ void __launch_bounds__(256, 2)
hgemm_nt(const __half* __restrict__ A, const __half* __restrict__ B,
         const float* __restrict__ bias, float* __restrict__ C,
         __half* __restrict__ Qe, __half* __restrict__ Ke,
         const float* __restrict__ pb,
         int Nld, int K, int lda, int ldb,
         size_t strA, size_t strB, size_t strC)
{
    extern __shared__ float dynsmem[];
    const uint32_t sb = smem_u32(dynsmem);

    const int tid  = threadIdx.x;
    const int wid  = tid >> 5;
    const int lane = tid & 31;

    A += strA * blockIdx.z;
    B += strB * blockIdx.z;
    C += strC * blockIdx.z;
    const int tileM = blockIdx.y * 128;
    const int tileN = blockIdx.x * 128;

    // ---- loader: thread covers rows baseRow + 32*i (i<4), 16B seg of 128B row
    const int baseRow = tid >> 3;      // 0..31
    const int seg     = tid & 7;       // 0..7
    const __half* Ath = A + (size_t)(tileM + baseRow) * lda + seg * 8;
    const __half* Bth = B + (size_t)(tileN + baseRow) * ldb + seg * 8;
    const uint32_t thoff = (uint32_t)(baseRow * 144 + seg * 16);

#define ISSUE_STAGE(KT, S) do {                                               \
    uint32_t _sa = sb + (uint32_t)(S) * H_STAGE_BYTES + thoff;                \
    const __half* _ga = Ath + (size_t)(KT) * 64;                              \
    const __half* _gb = Bth + (size_t)(KT) * 64;                              \
    _Pragma("unroll")                                                         \
    for (int _i = 0; _i < 4; _i++)                                            \
        cpasync16(_sa + _i * (32u * 144u), _ga + (size_t)_i * 32 * lda);      \
    _Pragma("unroll")                                                         \
    for (int _i = 0; _i < 4; _i++)                                            \
        cpasync16(_sa + 18432u + _i * (32u * 144u), _gb + (size_t)_i * 32 * ldb); \
    asm volatile("cp.async.commit_group;" ::: "memory");                      \
} while (0)

    const int nkt = K >> 6;            // 64 halfs per k-tile
    ISSUE_STAGE(0, 0);
    ISSUE_STAGE(1, 1);

    // ---- compute mapping
    const int warp_m = wid >> 2;       // 0..1  -> 64 rows
    const int warp_n = wid & 3;        // 0..3  -> 32 cols
    const int g   = lane >> 2;         // 0..7
    const int tig = lane & 3;          // 0..3

    const uint32_t laneA = (uint32_t)((lane & 15) * 144 + (lane >> 4) * 16);
    const uint32_t laneB = (uint32_t)(((lane & 7) + ((lane >> 4) & 1) * 8) * 144
                                      + ((lane >> 3) & 1) * 16);

#define LOAD_FRAGS(BUF, KS) do {                                              \
    uint32_t t0[4], t1[4];                                                    \
    _Pragma("unroll")                                                         \
    for (int _mi = 0; _mi < 4; _mi++)                                         \
        ldsm_x4(afr[BUF][_mi], aBase + _mi * 2304u + (KS) * 32u);             \
    ldsm_x4(t0, bBase + (KS) * 32u);                                          \
    ldsm_x4(t1, bBase + 2304u + (KS) * 32u);                                  \
    bfr[BUF][0][0] = t0[0]; bfr[BUF][0][1] = t0[1];                           \
    bfr[BUF][1][0] = t0[2]; bfr[BUF][1][1] = t0[3];                           \
    bfr[BUF][2][0] = t1[0]; bfr[BUF][2][1] = t1[1];                           \
    bfr[BUF][3][0] = t1[2]; bfr[BUF][3][1] = t1[3];                           \
} while (0)

    float acc[4][4][4];
#pragma unroll
    for (int mi = 0; mi < 4; mi++)
#pragma unroll
        for (int nj = 0; nj < 4; nj++)
#pragma unroll
            for (int r = 0; r < 4; r++) acc[mi][nj][r] = 0.0f;

    int s = 0;   // stage of tile kt
    for (int kt = 0; kt < nkt; ++kt) {
        if (kt + 2 < nkt) {
            asm volatile("cp.async.wait_group 1;" ::: "memory");
        } else {
            asm volatile("cp.async.wait_group 0;" ::: "memory");
        }
        __syncthreads();   // tile kt visible + all warps done with kt-1's stage

        if (kt + 2 < nkt) {
            const int s2 = (s + 2 >= 3) ? (s - 1) : (s + 2);
            ISSUE_STAGE(kt + 2, s2);
        }

        const uint32_t stAddr = sb + (uint32_t)s * H_STAGE_BYTES;
        const uint32_t aBase = stAddr + (uint32_t)(warp_m * 64) * 144 + laneA;
        const uint32_t bBase = stAddr + 18432u + (uint32_t)(warp_n * 32) * 144 + laneB;

        uint32_t afr[2][4][4];
        uint32_t bfr[2][4][2];
        LOAD_FRAGS(0, 0);

#pragma unroll
        for (int ks = 0; ks < 4; ++ks) {
            const int cur = ks & 1;
            if (ks < 3) LOAD_FRAGS(cur ^ 1, ks + 1);
#pragma unroll
            for (int mi = 0; mi < 4; mi++)
#pragma unroll
                for (int nj = 0; nj < 4; nj++)
                    mma_f16(acc[mi][nj], afr[cur][mi], bfr[cur][nj]);
        }
        s = (s + 1 == 3) ? 0 : (s + 1);
    }
#undef ISSUE_STAGE
#undef LOAD_FRAGS

    if (EPI == EPI_STORE) {
#pragma unroll
        for (int mi = 0; mi < 4; mi++) {
            const int row0 = tileM + warp_m * 64 + mi * 16 + g;
#pragma unroll
            for (int nj = 0; nj < 4; nj++) {
                const int col = tileN + warp_n * 32 + nj * 8 + 2 * tig;
                float2 bv = {0.0f, 0.0f};
                if (bias) bv = *(const float2*)(bias + col);
                float2 lo = { acc[mi][nj][0] + bv.x, acc[mi][nj][1] + bv.y };
                float2 hi = { acc[mi][nj][2] + bv.x, acc[mi][nj][3] + bv.y };
                *(float2*)(C + (size_t)row0 * Nld + col)       = lo;
                *(float2*)(C + (size_t)(row0 + 8) * Nld + col) = hi;
            }
        }
    } else {
        // EPI_THETA: acc = Q or K pre-bias, fp32-exact. col in [0,2048):
        // col < 1024 -> Q column d=col; col >= 1024 -> K column d=col-1024.
        // theta = (acc + bias) * inv_wl[d] + pb[d]; write cos->[m][d],
        // sin->[m][1024+d] as fp16 into Qe or Ke.
        const float WLC = (float)(6.283185307179586 / (double)DIM);
#pragma unroll
        for (int mi = 0; mi < 4; mi++) {
            const int row0 = tileM + warp_m * 64 + mi * 16 + g;
#pragma unroll
            for (int nj = 0; nj < 4; nj++) {
                const int col = tileN + warp_n * 32 + nj * 8 + 2 * tig;
                const int d   = col & (DIM - 1);
                __half* dst = (col < DIM) ? Qe : Ke;
                float2 bv = *(const float2*)(bias + col);
                float inv0 = 1.0f / ((float)(d + 1) * WLC + 1e-8f);
                float inv1 = 1.0f / ((float)(d + 2) * WLC + 1e-8f);
                float p0 = pb[d], p1 = pb[d + 1];
#pragma unroll
                for (int h = 0; h < 2; h++) {       // rows row0, row0+8
                    const int row = row0 + 8 * h;
                    float q0 = acc[mi][nj][2 * h + 0] + bv.x;
                    float q1 = acc[mi][nj][2 * h + 1] + bv.y;
                    float s0, c0, s1, c1;
                    sincosf(fmaf(q0, inv0, p0), &s0, &c0);
                    sincosf(fmaf(q1, inv1, p1), &s1, &c1);
                    __half* base = dst + (size_t)row * DE + d;
                    *(__half2*)(base)       = __floats2half2_rn(c0, c1);
                    *(__half2*)(base + DIM) = __floats2half2_rn(s0, s1);
                }
            }
        }
    }
}

// ---------------------------------------------------------------------------
// prep: fp16 split2 operands.
// A' = [xh | xh | xl]; Bqk rows (Wq then Wk): [Wh | Wl | Wh]; Bv = Wv fp16.
// ---------------------------------------------------------------------------
__global__ void __launch_bounds__(256)
convert_x(const float* __restrict__ x, __half* __restrict__ Ax)
{
    const int idx = blockIdx.x * blockDim.x + threadIdx.x;   // < MTOT*DIM
    const int m = idx >> 10;
    const int d = idx & (DIM - 1);
    float v = x[idx];
    __half h = __float2half_rn(v);
    __half l = __float2half_rn(v - __half2float(h));
    size_t base = (size_t)m * KQK;
    Ax[base + d]            = h;
    Ax[base + DIM + d]      = h;
    Ax[base + 2 * DIM + d]  = l;
}

__global__ void __launch_bounds__(256)
convert_w(const float* __restrict__ Wq, const float* __restrict__ Wk,
          const float* __restrict__ Wv,
          __half* __restrict__ Bqk, __half* __restrict__ Bv)
{
    const int idx = blockIdx.x * blockDim.x + threadIdx.x;   // < DIM*DIM
    const int n = idx >> 10;
    const int k = idx & (DIM - 1);
    // Wq -> rows [0,1024), Wk -> rows [1024,2048) of Bqk
    {
        float v = Wq[idx];
        __half h = __float2half_rn(v);
        __half l = __float2half_rn(v - __half2float(h));
        size_t base = (size_t)n * KQK;
        Bqk[base + k]           = h;
        Bqk[base + DIM + k]     = l;
        Bqk[base + 2 * DIM + k] = h;
    }
    {
        float v = Wk[idx];
        __half h = __float2half_rn(v);
        __half l = __float2half_rn(v - __half2float(h));
        size_t base = (size_t)(DIM + n) * KQK;
        Bqk[base + k]           = h;
        Bqk[base + DIM + k]     = l;
        Bqk[base + 2 * DIM + k] = h;
    }
    Bv[idx] = __float2half_rn(Wv[idx]);
}

__global__ void __launch_bounds__(256)
concat_bias(const float* __restrict__ bq, const float* __restrict__ bk,
            float* __restrict__ b2)
{
    const int i = blockIdx.x * blockDim.x + threadIdx.x;     // < DE
    b2[i] = (i < DIM) ? bq[i] : bk[i - DIM];
}

// ---------------------------------------------------------------------------
// V transpose per batch -> fp16: Vt[b][n][s] = fp16(V[b*4096+s][n])
// ---------------------------------------------------------------------------
__global__ void __launch_bounds__(256)
transpose_v(const float* __restrict__ V, __half* __restrict__ Vt)
{
    __shared__ float t[32][33];
    const int b  = blockIdx.z;
    const int s0 = blockIdx.y * 32;
    const int n0 = blockIdx.x * 32;
    const int x = threadIdx.x, y = threadIdx.y;   // 32 x 8
#pragma unroll
    for (int i = 0; i < 32; i += 8)
        t[y + i][x] = V[(size_t)(b * SEQ + s0 + y + i) * DIM + n0 + x];
    __syncthreads();
    __half* Vb = Vt + (size_t)b * DIM * SEQ;
#pragma unroll
    for (int i = 0; i < 32; i += 8)
        Vb[(size_t)(n0 + y + i) * SEQ + s0 + x] = __float2half_rn(t[x][y + i]);
}

// ---------------------------------------------------------------------------
// softmax rows (len SEQ), logits /32; writes fp16 weights to P.
// ---------------------------------------------------------------------------
__global__ void __launch_bounds__(256)
softmax_rows(const float* __restrict__ S, __half* __restrict__ P)
{
    __shared__ float sm[8];
    const float* p = S + (size_t)blockIdx.x * SEQ;
    __half* po = P + (size_t)blockIdx.x * SEQ;
    const float4* p4 = (const float4*)p;
    const int t    = threadIdx.x;
    const int lane = t & 31;
    const int wid  = t >> 5;
    const float SCALE = 0.03125f;   // 1/sqrt(1024)

    float v[16];
    float mx = -1e30f;
#pragma unroll
    for (int i = 0; i < 4; i++) {
        float4 x = p4[t + i * 256];
        v[4*i+0] = x.x * SCALE; v[4*i+1] = x.y * SCALE;
        v[4*i+2] = x.z * SCALE; v[4*i+3] = x.w * SCALE;
        mx = fmaxf(mx, fmaxf(fmaxf(v[4*i+0], v[4*i+1]),
                             fmaxf(v[4*i+2], v[4*i+3])));
    }
#pragma unroll
    for (int off = 16; off >= 1; off >>= 1)
        mx = fmaxf(mx, __shfl_xor_sync(0xffffffffu, mx, off));
    if (lane == 0) sm[wid] = mx;
    __syncthreads();
    mx = sm[0];
#pragma unroll
    for (int w = 1; w < 8; w++) mx = fmaxf(mx, sm[w]);
    __syncthreads();

    float sum = 0.0f;
#pragma unroll
    for (int i = 0; i < 16; i++) { v[i] = expf(v[i] - mx); sum += v[i]; }
#pragma unroll
    for (int off = 16; off >= 1; off >>= 1)
        sum += __shfl_xor_sync(0xffffffffu, sum, off);
    if (lane == 0) sm[wid] = sum;
    __syncthreads();
    sum = sm[0];
#pragma unroll
    for (int w = 1; w < 8; w++) sum += sm[w];
    float inv = 1.0f / sum;

    __half2* po2 = (__half2*)po;
#pragma unroll
    for (int i = 0; i < 4; i++) {
        const int e = 4 * (t + i * 256);
        po2[e / 2]     = __floats2half2_rn(v[4*i+0] * inv, v[4*i+1] * inv);
        po2[e / 2 + 1] = __floats2half2_rn(v[4*i+2] * inv, v[4*i+3] * inv);
    }
}

// ---------------------------------------------------------------------------
extern "C" void kernel_launch(void* const* d_in, const int* in_sizes, int n_in,
                              void* d_out, int out_size)
{
    const float* x  = (const float*)d_in[0];
    const float* Wq = (const float*)d_in[1];
    const float* bq = (const float*)d_in[2];
    const float* Wk = (const float*)d_in[3];
    const float* bk = (const float*)d_in[4];
    const float* Wv = (const float*)d_in[5];
    const float* bv = (const float*)d_in[6];
    const float* pb = (const float*)d_in[7];
    float* out = (float*)d_out;

    __half *Ax, *Bqk, *Bv, *Qe, *Ke, *Vt, *P;
    float *b2, *V, *Sm;
    cudaGetSymbolAddress((void**)&Ax,  g_Ax);
    cudaGetSymbolAddress((void**)&Bqk, g_Bqk);
    cudaGetSymbolAddress((void**)&Bv,  g_Bv);
    cudaGetSymbolAddress((void**)&b2,  g_bqk);
    cudaGetSymbolAddress((void**)&V,   g_V);
    cudaGetSymbolAddress((void**)&Qe,  g_Qe);
    cudaGetSymbolAddress((void**)&Ke,  g_Ke);
    cudaGetSymbolAddress((void**)&Vt,  g_Vt);
    cudaGetSymbolAddress((void**)&Sm,  g_S);
    cudaGetSymbolAddress((void**)&P,   g_P);

    cudaFuncSetAttribute(hgemm_nt<EPI_STORE>,
                         cudaFuncAttributeMaxDynamicSharedMemorySize,
                         H_SMEM_BYTES);
    cudaFuncSetAttribute(hgemm_nt<EPI_THETA>,
                         cudaFuncAttributeMaxDynamicSharedMemorySize,
                         H_SMEM_BYTES);

    // 0) build fp16 operands
    convert_x<<<(MTOT * DIM) / 256, 256>>>(x, Ax);
    convert_w<<<(DIM * DIM) / 256, 256>>>(Wq, Wk, Wv, Bqk, Bv);
    concat_bias<<<DE / 256, 256>>>(bq, bk, b2);

    // 1) QK projection (split2, K=3072) with fused theta epilogue -> Qe, Ke
    dim3 gQK(DE / 128, MTOT / 128, 1);
    hgemm_nt<EPI_THETA><<<gQK, 256, H_SMEM_BYTES>>>(
        Ax, Bqk, b2, nullptr, Qe, Ke, pb,
        DE, KQK, KQK, KQK, 0, 0, 0);

    // 2) V projection (plain fp16, K=1024) -> V fp32
    dim3 gV(DIM / 128, MTOT / 128, 1);
    hgemm_nt<EPI_STORE><<<gV, 256, H_SMEM_BYTES>>>(
        Ax, Bv, bv, V, nullptr, nullptr, nullptr,
        DIM, DIM, KQK, DIM, 0, 0, 0);

    // 3) V transpose -> fp16 [DIM][SEQ] per batch
    dim3 gT(DIM / 32, SEQ / 32, BATCH);
    transpose_v<<<gT, dim3(32, 8)>>>(V, Vt);

    // 4) sim = Qe @ Ke^T per batch (fp16 mma k16)
    dim3 gSim(SEQ / 128, SEQ / 128, BATCH);
    hgemm_nt<EPI_STORE><<<gSim, 256, H_SMEM_BYTES>>>(
        Qe, Ke, nullptr, Sm, nullptr, nullptr, nullptr,
        SEQ, DE, DE, DE,
        (size_t)SEQ * DE, (size_t)SEQ * DE, (size_t)SEQ * SEQ);

    // 5) softmax(sim / 32) rows -> fp16 weights
    softmax_rows<<<BATCH * SEQ, 256>>>(Sm, P);

    // 6) out = P @ Vt^T per batch (fp16 mma k16)
    dim3 gPV(DIM / 128, SEQ / 128, BATCH);
    hgemm_nt<EPI_STORE><<<gPV, 256, H_SMEM_BYTES>>>(
        P, Vt, nullptr, out, nullptr, nullptr, nullptr,
        DIM, SEQ, SEQ, SEQ,
        (size_t)SEQ * SEQ, (size_t)DIM * SEQ, (size_t)SEQ * DIM);
}